// round 1
// baseline (speedup 1.0000x reference)
#include <cuda_runtime.h>
#include <cstdint>
#include <cstddef>

// Problem constants
#define NS 64          // state dim
#define MO 32          // obs dim
#define NSIG 129       // 2n+1 sigma points
#define NSIGP 132      // padded to multiple of 4
#define TSTEPS 250
#define NTRAJ 128
#define PN 65          // padded row stride for width-64 matrices
#define PM 33          // padded row stride for width-32 matrices
#define DTC 0.02f
#define NLAM 63.0f                 // n + lambda (lambda = -1)
#define CW (0.5f/63.0f)            // tail weight (same for Wm and Wc)
#define WM0 (-1.0f/63.0f)
#define WC0 (2.0f - 1.0f/63.0f)    // Wm0 + (1 - a^2 + b) = -1/63 + 2

#define XS_OFF 2048000ULL          // 128*250*64
#define PS_SZ  131072000ULL        // 128*250*64*64

struct SM {
    float F[NS][PN];
    float H[MO][PN];
    float P[NS][PN];
    float L[NS][PN];       // chol workspace; later P_new scratch
    float sig[NSIGP][PN];  // sigma points; later w-scaled dxs
    float sf[NSIGP][PN];   // propagated sigma points; later dxs
    float zs[NSIGP][PM];   // obs sigma points; later dzs
    float Pz[MO][PM];      // innovation cov; chol in place
    float Pzc[MO][PM];     // copy of original Pz
    float Pxz[NS][PM];
    float Kw[NS][PM];      // Kalman gain
    float Mw[NS][PM];      // K * Pz
    float x[NS];
    float xp[NS];
    float zp[MO];
    float innov[MO];
    float zinv[MO];
    float red[256];
};

__device__ float g_mse[NTRAJ];

__global__ __launch_bounds__(256, 1)
void ukf_kernel(const float* __restrict__ gX, const float* __restrict__ gY,
                const float* __restrict__ gF, const float* __restrict__ gH,
                const float* __restrict__ gQ, const float* __restrict__ gR,
                float* __restrict__ out, int write_xs, int write_ps)
{
    extern __shared__ unsigned char smem_raw[];
    SM& s = *reinterpret_cast<SM*>(smem_raw);

    const int tid = threadIdx.x;
    const int traj = blockIdx.x;

    // ---- init ----
    for (int idx = tid; idx < NS*NS; idx += 256) {
        int i = idx >> 6, j = idx & 63;
        s.F[i][j] = gF[idx];
        s.P[i][j] = (i == j) ? 1e-5f : 0.0f;
    }
    for (int idx = tid; idx < MO*NS; idx += 256) {
        int i = idx >> 6, j = idx & 63;
        s.H[i][j] = gH[idx];
    }
    if (tid < NS) s.x[tid] = 0.0f;
    // zero padding rows of sig (rows 129..131) once; never rewritten
    for (int idx = tid; idx < 3*PN; idx += 256) {
        int r = NSIG + idx / PN, c = idx % PN;
        s.sig[r][c] = 0.0f;
    }
    float mse_acc = 0.0f;
    __syncthreads();

    for (int t = 0; t < TSTEPS; ++t) {
        // ---- phase 1: A = 63*(P + 1e-8 I) into L ----
        for (int idx = tid; idx < NS*NS; idx += 256) {
            int i = idx >> 6, j = idx & 63;
            float v = s.P[i][j];
            if (i == j) v += 1e-8f;
            s.L[i][j] = NLAM * v;
        }
        __syncthreads();

        // ---- phase 2: Cholesky 64 (left-looking, row per thread) ----
        for (int j = 0; j < NS; ++j) {
            if (tid < NS && tid >= j) {
                const float* ri = s.L[tid];
                const float* rj = s.L[j];
                float s0 = 0.f, s1 = 0.f, s2 = 0.f, s3 = 0.f;
                int k = 0;
                for (; k + 4 <= j; k += 4) {
                    s0 += ri[k]   * rj[k];
                    s1 += ri[k+1] * rj[k+1];
                    s2 += ri[k+2] * rj[k+2];
                    s3 += ri[k+3] * rj[k+3];
                }
                for (; k < j; ++k) s0 += ri[k] * rj[k];
                s.red[tid] = s.L[tid][j] - ((s0 + s1) + (s2 + s3));
            }
            __syncthreads();
            float dval = sqrtf(s.red[j]);
            if (tid < NS) {
                if (tid > j)       s.L[tid][j] = s.red[tid] / dval;
                else if (tid == j) s.L[j][j] = dval;
                else               s.L[tid][j] = 0.0f;  // zero strict upper
            }
            __syncthreads();
        }

        // ---- phase 3: sigma points ----
        for (int idx = tid; idx < NSIG*NS; idx += 256) {
            int ss = idx >> 6, d = idx & 63;
            float v = s.x[d];
            if (ss >= 1) {
                if (ss <= NS) v += s.L[d][ss-1];
                else          v -= s.L[d][ss-1-NS];
            }
            s.sig[ss][d] = v;
        }
        __syncthreads();

        // ---- phase 4: propagate sf = sig + DT*tanh(sig @ F^T), 4s x 4d tiles ----
        for (int tt = tid; tt < 33*16; tt += 256) {
            int sq = tt >> 4, q = tt & 15;
            int s0r = sq * 4;
            float a[4][4];
            #pragma unroll
            for (int r = 0; r < 4; ++r)
                #pragma unroll
                for (int c = 0; c < 4; ++c) a[r][c] = 0.0f;
            for (int e = 0; e < NS; ++e) {
                float f0 = s.F[q][e], f1 = s.F[q+16][e], f2 = s.F[q+32][e], f3 = s.F[q+48][e];
                #pragma unroll
                for (int r = 0; r < 4; ++r) {
                    float sv = s.sig[s0r+r][e];
                    a[r][0] += f0 * sv; a[r][1] += f1 * sv;
                    a[r][2] += f2 * sv; a[r][3] += f3 * sv;
                }
            }
            #pragma unroll
            for (int r = 0; r < 4; ++r)
                #pragma unroll
                for (int c = 0; c < 4; ++c) {
                    int d = q + 16*c;
                    s.sf[s0r+r][d] = s.sig[s0r+r][d] + DTC * tanhf(a[r][c]);
                }
        }
        __syncthreads();

        // ---- phase 5: zs = sf @ H^T, 4s x 4m tiles ----
        for (int tt = tid; tt < 33*8; tt += 256) {
            int sq = tt >> 3, q = tt & 7;
            int s0r = sq * 4;
            float a[4][4];
            #pragma unroll
            for (int r = 0; r < 4; ++r)
                #pragma unroll
                for (int c = 0; c < 4; ++c) a[r][c] = 0.0f;
            for (int e = 0; e < NS; ++e) {
                float h0 = s.H[q][e], h1 = s.H[q+8][e], h2 = s.H[q+16][e], h3 = s.H[q+24][e];
                #pragma unroll
                for (int r = 0; r < 4; ++r) {
                    float sv = s.sf[s0r+r][e];
                    a[r][0] += h0 * sv; a[r][1] += h1 * sv;
                    a[r][2] += h2 * sv; a[r][3] += h3 * sv;
                }
            }
            #pragma unroll
            for (int r = 0; r < 4; ++r)
                #pragma unroll
                for (int c = 0; c < 4; ++c)
                    s.zs[s0r+r][q + 8*c] = a[r][c];
        }
        __syncthreads();

        // ---- phase 6: x_pred (threads 0..63), z_pred (threads 64..95) ----
        if (tid < NS) {
            float a0 = WM0 * s.sf[0][tid];
            float t1 = 0.f, t2 = 0.f, t3 = 0.f, t4 = 0.f;
            for (int k = 1; k + 4 <= NSIG; k += 4) {
                t1 += s.sf[k][tid];   t2 += s.sf[k+1][tid];
                t3 += s.sf[k+2][tid]; t4 += s.sf[k+3][tid];
            }
            s.xp[tid] = a0 + CW * ((t1 + t2) + (t3 + t4));
        } else if (tid < NS + MO) {
            int m = tid - NS;
            float a0 = WM0 * s.zs[0][m];
            float t1 = 0.f, t2 = 0.f, t3 = 0.f, t4 = 0.f;
            for (int k = 1; k + 4 <= NSIG; k += 4) {
                t1 += s.zs[k][m];   t2 += s.zs[k+1][m];
                t3 += s.zs[k+2][m]; t4 += s.zs[k+3][m];
            }
            s.zp[m] = a0 + CW * ((t1 + t2) + (t3 + t4));
        }
        __syncthreads();

        // ---- phase 7: dxs (+ w-scaled copy into sig), dzs, innovation ----
        for (int idx = tid; idx < NSIG*NS; idx += 256) {
            int k2 = idx >> 6, d = idx & 63;
            float dx = s.sf[k2][d] - s.xp[d];
            s.sf[k2][d] = dx;
            s.sig[k2][d] = ((k2 == 0) ? WC0 : CW) * dx;
        }
        for (int idx = tid; idx < NSIG*MO; idx += 256) {
            int k2 = idx >> 5, m2 = idx & 31;
            s.zs[k2][m2] -= s.zp[m2];
        }
        if (tid >= 224) {
            int m2 = tid - 224;
            s.innov[m2] = gY[(size_t)traj * TSTEPS * MO + (size_t)t * MO + m2] - s.zp[m2];
        }
        __syncthreads();

        // ---- phase 8: P_pred gram (4x4 tile / thread) ----
        {
            int ti = tid & 15, tj = tid >> 4;
            float acc[4][4];
            #pragma unroll
            for (int r = 0; r < 4; ++r)
                #pragma unroll
                for (int c = 0; c < 4; ++c) acc[r][c] = 0.0f;
            for (int k2 = 0; k2 < NSIG; ++k2) {
                float a0 = s.sig[k2][ti],    a1 = s.sig[k2][ti+16];
                float a2 = s.sig[k2][ti+32], a3 = s.sig[k2][ti+48];
                float b0 = s.sf[k2][tj],     b1 = s.sf[k2][tj+16];
                float b2 = s.sf[k2][tj+32],  b3 = s.sf[k2][tj+48];
                acc[0][0] += a0*b0; acc[0][1] += a0*b1; acc[0][2] += a0*b2; acc[0][3] += a0*b3;
                acc[1][0] += a1*b0; acc[1][1] += a1*b1; acc[1][2] += a1*b2; acc[1][3] += a1*b3;
                acc[2][0] += a2*b0; acc[2][1] += a2*b1; acc[2][2] += a2*b2; acc[2][3] += a2*b3;
                acc[3][0] += a3*b0; acc[3][1] += a3*b1; acc[3][2] += a3*b2; acc[3][3] += a3*b3;
            }
            #pragma unroll
            for (int r = 0; r < 4; ++r)
                #pragma unroll
                for (int c = 0; c < 4; ++c) {
                    int i = ti + 16*r, j = tj + 16*c;
                    s.P[i][j] = acc[r][c] + gQ[i*NS + j];
                }
        }
        // ---- phase 9: Pz gram (2x2) ----
        {
            int ti = tid & 15, tj = tid >> 4;
            float acc[2][2] = {{0.f,0.f},{0.f,0.f}};
            for (int k2 = 0; k2 < NSIG; ++k2) {
                float w = (k2 == 0) ? WC0 : CW;
                float a0 = w * s.zs[k2][ti], a1 = w * s.zs[k2][ti+16];
                float b0 = s.zs[k2][tj],     b1 = s.zs[k2][tj+16];
                acc[0][0] += a0*b0; acc[0][1] += a0*b1;
                acc[1][0] += a1*b0; acc[1][1] += a1*b1;
            }
            #pragma unroll
            for (int r = 0; r < 2; ++r)
                #pragma unroll
                for (int c = 0; c < 2; ++c) {
                    int i = ti + 16*r, j = tj + 16*c;
                    s.Pz[i][j] = acc[r][c] + gR[i*MO + j];
                }
        }
        // ---- phase 10: Pxz gram (2i x 4m) ----
        {
            int ti = tid & 31, tj = tid >> 5;
            float acc[2][4];
            #pragma unroll
            for (int r = 0; r < 2; ++r)
                #pragma unroll
                for (int c = 0; c < 4; ++c) acc[r][c] = 0.0f;
            for (int k2 = 0; k2 < NSIG; ++k2) {
                float a0 = s.sig[k2][ti], a1 = s.sig[k2][ti+32];
                float b0 = s.zs[k2][tj],    b1 = s.zs[k2][tj+8];
                float b2 = s.zs[k2][tj+16], b3 = s.zs[k2][tj+24];
                acc[0][0] += a0*b0; acc[0][1] += a0*b1; acc[0][2] += a0*b2; acc[0][3] += a0*b3;
                acc[1][0] += a1*b0; acc[1][1] += a1*b1; acc[1][2] += a1*b2; acc[1][3] += a1*b3;
            }
            #pragma unroll
            for (int r = 0; r < 2; ++r)
                #pragma unroll
                for (int c = 0; c < 4; ++c)
                    s.Pxz[ti + 32*r][tj + 8*c] = acc[r][c];
        }
        __syncthreads();

        // ---- phase 11: copy Pz before factoring ----
        for (int idx = tid; idx < MO*MO; idx += 256) {
            int i = idx >> 5, j = idx & 31;
            s.Pzc[i][j] = s.Pz[i][j];
        }
        __syncthreads();

        // ---- phase 12: Cholesky 32 on Pz ----
        for (int j = 0; j < MO; ++j) {
            if (tid < MO && tid >= j) {
                const float* ri = s.Pz[tid];
                const float* rj = s.Pz[j];
                float s0 = 0.f, s1 = 0.f;
                int k = 0;
                for (; k + 2 <= j; k += 2) { s0 += ri[k]*rj[k]; s1 += ri[k+1]*rj[k+1]; }
                for (; k < j; ++k) s0 += ri[k]*rj[k];
                s.red[tid] = s.Pz[tid][j] - (s0 + s1);
            }
            __syncthreads();
            float dval = sqrtf(s.red[j]);
            if (tid < MO) {
                if (tid > j)       s.Pz[tid][j] = s.red[tid] / dval;
                else if (tid == j) { s.Pz[j][j] = dval; s.zinv[j] = 1.0f / dval; }
                else               s.Pz[tid][j] = 0.0f;
            }
            __syncthreads();
        }

        // ---- phase 13: per-row triangular solves -> K, fused x_new ----
        if (tid < NS) {
            float v[MO];
            #pragma unroll
            for (int m2 = 0; m2 < MO; ++m2) v[m2] = s.Pxz[tid][m2];
            #pragma unroll
            for (int i = 0; i < MO; ++i) {
                float acc = v[i];
                #pragma unroll
                for (int j2 = 0; j2 < i; ++j2) acc -= s.Pz[i][j2] * v[j2];
                v[i] = acc * s.zinv[i];
            }
            #pragma unroll
            for (int i = MO - 1; i >= 0; --i) {
                float acc = v[i];
                #pragma unroll
                for (int j2 = i + 1; j2 < MO; ++j2) acc -= s.Pz[j2][i] * v[j2];
                v[i] = acc * s.zinv[i];
            }
            float xn = s.xp[tid];
            #pragma unroll
            for (int m2 = 0; m2 < MO; ++m2) {
                xn += v[m2] * s.innov[m2];
                s.Kw[tid][m2] = v[m2];
            }
            s.x[tid] = xn;
            size_t oidx = ((size_t)traj * TSTEPS + t) * NS + tid;
            if (write_xs) out[oidx] = xn;
            float de = xn - gX[oidx];
            mse_acc += de * de;
        }
        __syncthreads();

        // ---- phase 14: M = K * Pzc (2i x 4m tiles) ----
        {
            int ti = tid & 31, tj = tid >> 5;
            float acc[2][4];
            #pragma unroll
            for (int r = 0; r < 2; ++r)
                #pragma unroll
                for (int c = 0; c < 4; ++c) acc[r][c] = 0.0f;
            for (int p = 0; p < MO; ++p) {
                float a0 = s.Kw[ti][p], a1 = s.Kw[ti+32][p];
                float b0 = s.Pzc[p][tj],    b1 = s.Pzc[p][tj+8];
                float b2 = s.Pzc[p][tj+16], b3 = s.Pzc[p][tj+24];
                acc[0][0] += a0*b0; acc[0][1] += a0*b1; acc[0][2] += a0*b2; acc[0][3] += a0*b3;
                acc[1][0] += a1*b0; acc[1][1] += a1*b1; acc[1][2] += a1*b2; acc[1][3] += a1*b3;
            }
            #pragma unroll
            for (int r = 0; r < 2; ++r)
                #pragma unroll
                for (int c = 0; c < 4; ++c)
                    s.Mw[ti + 32*r][tj + 8*c] = acc[r][c];
        }
        __syncthreads();

        // ---- phase 15: P_new = P_pred - M K^T into L (4x4 tiles) ----
        {
            int ti = tid & 15, tj = tid >> 4;
            float acc[4][4];
            #pragma unroll
            for (int r = 0; r < 4; ++r)
                #pragma unroll
                for (int c = 0; c < 4; ++c) acc[r][c] = 0.0f;
            for (int m2 = 0; m2 < MO; ++m2) {
                float a0 = s.Mw[ti][m2],    a1 = s.Mw[ti+16][m2];
                float a2 = s.Mw[ti+32][m2], a3 = s.Mw[ti+48][m2];
                float b0 = s.Kw[tj][m2],    b1 = s.Kw[tj+16][m2];
                float b2 = s.Kw[tj+32][m2], b3 = s.Kw[tj+48][m2];
                acc[0][0] += a0*b0; acc[0][1] += a0*b1; acc[0][2] += a0*b2; acc[0][3] += a0*b3;
                acc[1][0] += a1*b0; acc[1][1] += a1*b1; acc[1][2] += a1*b2; acc[1][3] += a1*b3;
                acc[2][0] += a2*b0; acc[2][1] += a2*b1; acc[2][2] += a2*b2; acc[2][3] += a2*b3;
                acc[3][0] += a3*b0; acc[3][1] += a3*b1; acc[3][2] += a3*b2; acc[3][3] += a3*b3;
            }
            #pragma unroll
            for (int r = 0; r < 4; ++r)
                #pragma unroll
                for (int c = 0; c < 4; ++c) {
                    int i = ti + 16*r, j = tj + 16*c;
                    s.L[i][j] = s.P[i][j] - acc[r][c];
                }
        }
        __syncthreads();

        // ---- phase 16: symmetrize into P, optionally write Ps ----
        for (int idx = tid; idx < NS*NS; idx += 256) {
            int i = idx >> 6, j = idx & 63;
            float v = 0.5f * (s.L[i][j] + s.L[j][i]);
            s.P[i][j] = v;
            if (write_ps)
                out[XS_OFF + (((size_t)traj * TSTEPS + t) << 12) + idx] = v;
        }
        __syncthreads();
    }

    // ---- per-trajectory MSE ----
    if (tid < NS) s.red[tid] = mse_acc; else s.red[tid] = 0.0f;
    __syncthreads();
    if (tid == 0) {
        float tot = 0.0f;
        for (int i = 0; i < NS; ++i) tot += s.red[i];
        g_mse[traj] = tot * (1.0f / (float)(TSTEPS * NS));
    }
}

__global__ void finalize_kernel(float* __restrict__ out, unsigned long long out_size)
{
    __shared__ float sh[NTRAJ];
    int tid = threadIdx.x;
    sh[tid] = g_mse[tid];
    __syncthreads();
    if (tid == 0) {
        float tot = 0.0f;
        for (int i = 0; i < NTRAJ; ++i) tot += sh[i];
        float lin = tot / (float)NTRAJ;
        float db = 10.0f * log10f(lin);
        const unsigned long long XS = XS_OFF, PS = PS_SZ;
        if (out_size >= XS + PS + 2ULL) { out[XS+PS] = lin; out[XS+PS+1ULL] = db; }
        else if (out_size == XS + 2ULL) { out[XS] = lin; out[XS+1ULL] = db; }
        else if (out_size == 2ULL)      { out[0] = lin; out[1] = db; }
        else if (out_size == 1ULL)      { out[0] = db; }
    }
}

extern "C" void kernel_launch(void* const* d_in, const int* in_sizes, int n_in,
                              void* d_out, int out_size)
{
    const float* X = (const float*)d_in[0];
    const float* Y = (const float*)d_in[1];
    const float* F = (const float*)d_in[2];
    const float* H = (const float*)d_in[3];
    const float* Q = (const float*)d_in[4];
    const float* R = (const float*)d_in[5];
    float* out = (float*)d_out;

    unsigned long long os = (unsigned long long)(long long)out_size;
    int wxs = (os >= XS_OFF) ? 1 : 0;
    int wps = (os >= XS_OFF + PS_SZ) ? 1 : 0;

    cudaFuncSetAttribute(ukf_kernel, cudaFuncAttributeMaxDynamicSharedMemorySize,
                         (int)sizeof(SM));
    ukf_kernel<<<NTRAJ, 256, sizeof(SM)>>>(X, Y, F, H, Q, R, out, wxs, wps);
    finalize_kernel<<<1, NTRAJ>>>(out, os);
}

// round 2
// speedup vs baseline: 1.0009x; 1.0009x over previous
#include <cuda_runtime.h>
#include <cstdint>
#include <cstddef>

// Problem constants
#define NS 64          // state dim
#define MO 32          // obs dim
#define NSIG 129       // 2n+1 sigma points
#define NSIGP 132      // padded to multiple of 4
#define TSTEPS 250
#define NTRAJ 128
#define PN 65          // padded row stride for width-64 matrices
#define PM 33          // padded row stride for width-32 matrices
#define DTC 0.02f
#define NLAM 63.0f                 // n + lambda (lambda = -1)
#define CW (0.5f/63.0f)            // tail weight (same for Wm and Wc)
#define WM0 (-1.0f/63.0f)
#define WC0 (2.0f - 1.0f/63.0f)    // Wm0 + (1 - a^2 + b) = -1/63 + 2

#define XS_OFF 2048000ULL          // 128*250*64
#define PS_SZ  131072000ULL        // 128*250*64*64

struct SM {
    float F[NS][PN];
    float H[MO][PN];
    float P[NS][PN];
    float L[NS][PN];       // chol workspace; later P_new scratch
    float sig[NSIGP][PN];  // sigma points; later w-scaled dxs
    float sf[NSIGP][PN];   // propagated sigma points; later dxs
    float zs[NSIGP][PM];   // obs sigma points; later dzs
    float Pz[MO][PM];      // innovation cov; chol in place
    float Pzc[MO][PM];     // copy of original Pz
    float Pxz[NS][PM];
    float Kw[NS][PM];      // Kalman gain
    float Mw[NS][PM];      // K * Pz
    float x[NS];
    float xp[NS];
    float zp[MO];
    float innov[MO];
    float zinv[MO];
    float red[256];
};

__device__ float g_mse[NTRAJ];

__global__ __launch_bounds__(256, 1)
void ukf_kernel(const float* __restrict__ gX, const float* __restrict__ gY,
                const float* __restrict__ gF, const float* __restrict__ gH,
                const float* __restrict__ gQ, const float* __restrict__ gR,
                float* __restrict__ out, int write_xs, int write_ps)
{
    extern __shared__ unsigned char smem_raw[];
    SM& s = *reinterpret_cast<SM*>(smem_raw);

    const int tid = threadIdx.x;
    const int traj = blockIdx.x;

    // ---- init ----
    for (int idx = tid; idx < NS*NS; idx += 256) {
        int i = idx >> 6, j = idx & 63;
        s.F[i][j] = gF[idx];
        s.P[i][j] = (i == j) ? 1e-5f : 0.0f;
    }
    for (int idx = tid; idx < MO*NS; idx += 256) {
        int i = idx >> 6, j = idx & 63;
        s.H[i][j] = gH[idx];
    }
    if (tid < NS) s.x[tid] = 0.0f;
    // zero padding rows of sig (rows 129..131) once; never rewritten
    for (int idx = tid; idx < 3*PN; idx += 256) {
        int r = NSIG + idx / PN, c = idx % PN;
        s.sig[r][c] = 0.0f;
    }
    float mse_acc = 0.0f;
    __syncthreads();

    for (int t = 0; t < TSTEPS; ++t) {
        // ---- phase 1: A = 63*(P + 1e-8 I) into L ----
        for (int idx = tid; idx < NS*NS; idx += 256) {
            int i = idx >> 6, j = idx & 63;
            float v = s.P[i][j];
            if (i == j) v += 1e-8f;
            s.L[i][j] = NLAM * v;
        }
        __syncthreads();

        // ---- phase 2: Cholesky 64 (left-looking, row per thread) ----
        for (int j = 0; j < NS; ++j) {
            if (tid < NS && tid >= j) {
                const float* ri = s.L[tid];
                const float* rj = s.L[j];
                float s0 = 0.f, s1 = 0.f, s2 = 0.f, s3 = 0.f;
                int k = 0;
                for (; k + 4 <= j; k += 4) {
                    s0 += ri[k]   * rj[k];
                    s1 += ri[k+1] * rj[k+1];
                    s2 += ri[k+2] * rj[k+2];
                    s3 += ri[k+3] * rj[k+3];
                }
                for (; k < j; ++k) s0 += ri[k] * rj[k];
                s.red[tid] = s.L[tid][j] - ((s0 + s1) + (s2 + s3));
            }
            __syncthreads();
            float dval = sqrtf(s.red[j]);
            if (tid < NS) {
                if (tid > j)       s.L[tid][j] = s.red[tid] / dval;
                else if (tid == j) s.L[j][j] = dval;
                else               s.L[tid][j] = 0.0f;  // zero strict upper
            }
            __syncthreads();
        }

        // ---- phase 3: sigma points ----
        for (int idx = tid; idx < NSIG*NS; idx += 256) {
            int ss = idx >> 6, d = idx & 63;
            float v = s.x[d];
            if (ss >= 1) {
                if (ss <= NS) v += s.L[d][ss-1];
                else          v -= s.L[d][ss-1-NS];
            }
            s.sig[ss][d] = v;
        }
        __syncthreads();

        // ---- phase 4: propagate sf = sig + DT*tanh(sig @ F^T), 4s x 4d tiles ----
        for (int tt = tid; tt < 33*16; tt += 256) {
            int sq = tt >> 4, q = tt & 15;
            int s0r = sq * 4;
            float a[4][4];
            #pragma unroll
            for (int r = 0; r < 4; ++r)
                #pragma unroll
                for (int c = 0; c < 4; ++c) a[r][c] = 0.0f;
            for (int e = 0; e < NS; ++e) {
                float f0 = s.F[q][e], f1 = s.F[q+16][e], f2 = s.F[q+32][e], f3 = s.F[q+48][e];
                #pragma unroll
                for (int r = 0; r < 4; ++r) {
                    float sv = s.sig[s0r+r][e];
                    a[r][0] += f0 * sv; a[r][1] += f1 * sv;
                    a[r][2] += f2 * sv; a[r][3] += f3 * sv;
                }
            }
            #pragma unroll
            for (int r = 0; r < 4; ++r)
                #pragma unroll
                for (int c = 0; c < 4; ++c) {
                    int d = q + 16*c;
                    s.sf[s0r+r][d] = s.sig[s0r+r][d] + DTC * tanhf(a[r][c]);
                }
        }
        __syncthreads();

        // ---- phase 5: zs = sf @ H^T, 4s x 4m tiles ----
        for (int tt = tid; tt < 33*8; tt += 256) {
            int sq = tt >> 3, q = tt & 7;
            int s0r = sq * 4;
            float a[4][4];
            #pragma unroll
            for (int r = 0; r < 4; ++r)
                #pragma unroll
                for (int c = 0; c < 4; ++c) a[r][c] = 0.0f;
            for (int e = 0; e < NS; ++e) {
                float h0 = s.H[q][e], h1 = s.H[q+8][e], h2 = s.H[q+16][e], h3 = s.H[q+24][e];
                #pragma unroll
                for (int r = 0; r < 4; ++r) {
                    float sv = s.sf[s0r+r][e];
                    a[r][0] += h0 * sv; a[r][1] += h1 * sv;
                    a[r][2] += h2 * sv; a[r][3] += h3 * sv;
                }
            }
            #pragma unroll
            for (int r = 0; r < 4; ++r)
                #pragma unroll
                for (int c = 0; c < 4; ++c)
                    s.zs[s0r+r][q + 8*c] = a[r][c];
        }
        __syncthreads();

        // ---- phase 6: x_pred (threads 0..63), z_pred (threads 64..95) ----
        if (tid < NS) {
            float a0 = WM0 * s.sf[0][tid];
            float t1 = 0.f, t2 = 0.f, t3 = 0.f, t4 = 0.f;
            for (int k = 1; k + 4 <= NSIG; k += 4) {
                t1 += s.sf[k][tid];   t2 += s.sf[k+1][tid];
                t3 += s.sf[k+2][tid]; t4 += s.sf[k+3][tid];
            }
            s.xp[tid] = a0 + CW * ((t1 + t2) + (t3 + t4));
        } else if (tid < NS + MO) {
            int m = tid - NS;
            float a0 = WM0 * s.zs[0][m];
            float t1 = 0.f, t2 = 0.f, t3 = 0.f, t4 = 0.f;
            for (int k = 1; k + 4 <= NSIG; k += 4) {
                t1 += s.zs[k][m];   t2 += s.zs[k+1][m];
                t3 += s.zs[k+2][m]; t4 += s.zs[k+3][m];
            }
            s.zp[m] = a0 + CW * ((t1 + t2) + (t3 + t4));
        }
        __syncthreads();

        // ---- phase 7: dxs (+ w-scaled copy into sig), dzs, innovation ----
        for (int idx = tid; idx < NSIG*NS; idx += 256) {
            int k2 = idx >> 6, d = idx & 63;
            float dx = s.sf[k2][d] - s.xp[d];
            s.sf[k2][d] = dx;
            s.sig[k2][d] = ((k2 == 0) ? WC0 : CW) * dx;
        }
        for (int idx = tid; idx < NSIG*MO; idx += 256) {
            int k2 = idx >> 5, m2 = idx & 31;
            s.zs[k2][m2] -= s.zp[m2];
        }
        if (tid >= 224) {
            int m2 = tid - 224;
            s.innov[m2] = gY[(size_t)traj * TSTEPS * MO + (size_t)t * MO + m2] - s.zp[m2];
        }
        __syncthreads();

        // ---- phase 8: P_pred gram (4x4 tile / thread) ----
        {
            int ti = tid & 15, tj = tid >> 4;
            float acc[4][4];
            #pragma unroll
            for (int r = 0; r < 4; ++r)
                #pragma unroll
                for (int c = 0; c < 4; ++c) acc[r][c] = 0.0f;
            for (int k2 = 0; k2 < NSIG; ++k2) {
                float a0 = s.sig[k2][ti],    a1 = s.sig[k2][ti+16];
                float a2 = s.sig[k2][ti+32], a3 = s.sig[k2][ti+48];
                float b0 = s.sf[k2][tj],     b1 = s.sf[k2][tj+16];
                float b2 = s.sf[k2][tj+32],  b3 = s.sf[k2][tj+48];
                acc[0][0] += a0*b0; acc[0][1] += a0*b1; acc[0][2] += a0*b2; acc[0][3] += a0*b3;
                acc[1][0] += a1*b0; acc[1][1] += a1*b1; acc[1][2] += a1*b2; acc[1][3] += a1*b3;
                acc[2][0] += a2*b0; acc[2][1] += a2*b1; acc[2][2] += a2*b2; acc[2][3] += a2*b3;
                acc[3][0] += a3*b0; acc[3][1] += a3*b1; acc[3][2] += a3*b2; acc[3][3] += a3*b3;
            }
            #pragma unroll
            for (int r = 0; r < 4; ++r)
                #pragma unroll
                for (int c = 0; c < 4; ++c) {
                    int i = ti + 16*r, j = tj + 16*c;
                    s.P[i][j] = acc[r][c] + gQ[i*NS + j];
                }
        }
        // ---- phase 9: Pz gram (2x2) ----
        {
            int ti = tid & 15, tj = tid >> 4;
            float acc[2][2] = {{0.f,0.f},{0.f,0.f}};
            for (int k2 = 0; k2 < NSIG; ++k2) {
                float w = (k2 == 0) ? WC0 : CW;
                float a0 = w * s.zs[k2][ti], a1 = w * s.zs[k2][ti+16];
                float b0 = s.zs[k2][tj],     b1 = s.zs[k2][tj+16];
                acc[0][0] += a0*b0; acc[0][1] += a0*b1;
                acc[1][0] += a1*b0; acc[1][1] += a1*b1;
            }
            #pragma unroll
            for (int r = 0; r < 2; ++r)
                #pragma unroll
                for (int c = 0; c < 2; ++c) {
                    int i = ti + 16*r, j = tj + 16*c;
                    s.Pz[i][j] = acc[r][c] + gR[i*MO + j];
                }
        }
        // ---- phase 10: Pxz gram (2i x 4m) ----
        {
            int ti = tid & 31, tj = tid >> 5;
            float acc[2][4];
            #pragma unroll
            for (int r = 0; r < 2; ++r)
                #pragma unroll
                for (int c = 0; c < 4; ++c) acc[r][c] = 0.0f;
            for (int k2 = 0; k2 < NSIG; ++k2) {
                float a0 = s.sig[k2][ti], a1 = s.sig[k2][ti+32];
                float b0 = s.zs[k2][tj],    b1 = s.zs[k2][tj+8];
                float b2 = s.zs[k2][tj+16], b3 = s.zs[k2][tj+24];
                acc[0][0] += a0*b0; acc[0][1] += a0*b1; acc[0][2] += a0*b2; acc[0][3] += a0*b3;
                acc[1][0] += a1*b0; acc[1][1] += a1*b1; acc[1][2] += a1*b2; acc[1][3] += a1*b3;
            }
            #pragma unroll
            for (int r = 0; r < 2; ++r)
                #pragma unroll
                for (int c = 0; c < 4; ++c)
                    s.Pxz[ti + 32*r][tj + 8*c] = acc[r][c];
        }
        __syncthreads();

        // ---- phase 11: copy Pz before factoring ----
        for (int idx = tid; idx < MO*MO; idx += 256) {
            int i = idx >> 5, j = idx & 31;
            s.Pzc[i][j] = s.Pz[i][j];
        }
        __syncthreads();

        // ---- phase 12: Cholesky 32 on Pz ----
        for (int j = 0; j < MO; ++j) {
            if (tid < MO && tid >= j) {
                const float* ri = s.Pz[tid];
                const float* rj = s.Pz[j];
                float s0 = 0.f, s1 = 0.f;
                int k = 0;
                for (; k + 2 <= j; k += 2) { s0 += ri[k]*rj[k]; s1 += ri[k+1]*rj[k+1]; }
                for (; k < j; ++k) s0 += ri[k]*rj[k];
                s.red[tid] = s.Pz[tid][j] - (s0 + s1);
            }
            __syncthreads();
            float dval = sqrtf(s.red[j]);
            if (tid < MO) {
                if (tid > j)       s.Pz[tid][j] = s.red[tid] / dval;
                else if (tid == j) { s.Pz[j][j] = dval; s.zinv[j] = 1.0f / dval; }
                else               s.Pz[tid][j] = 0.0f;
            }
            __syncthreads();
        }

        // ---- phase 13: per-row triangular solves -> K, fused x_new ----
        if (tid < NS) {
            float v[MO];
            #pragma unroll
            for (int m2 = 0; m2 < MO; ++m2) v[m2] = s.Pxz[tid][m2];
            #pragma unroll
            for (int i = 0; i < MO; ++i) {
                float acc = v[i];
                #pragma unroll
                for (int j2 = 0; j2 < i; ++j2) acc -= s.Pz[i][j2] * v[j2];
                v[i] = acc * s.zinv[i];
            }
            #pragma unroll
            for (int i = MO - 1; i >= 0; --i) {
                float acc = v[i];
                #pragma unroll
                for (int j2 = i + 1; j2 < MO; ++j2) acc -= s.Pz[j2][i] * v[j2];
                v[i] = acc * s.zinv[i];
            }
            float xn = s.xp[tid];
            #pragma unroll
            for (int m2 = 0; m2 < MO; ++m2) {
                xn += v[m2] * s.innov[m2];
                s.Kw[tid][m2] = v[m2];
            }
            s.x[tid] = xn;
            size_t oidx = ((size_t)traj * TSTEPS + t) * NS + tid;
            if (write_xs) out[oidx] = xn;
            float de = xn - gX[oidx];
            mse_acc += de * de;
        }
        __syncthreads();

        // ---- phase 14: M = K * Pzc (2i x 4m tiles) ----
        {
            int ti = tid & 31, tj = tid >> 5;
            float acc[2][4];
            #pragma unroll
            for (int r = 0; r < 2; ++r)
                #pragma unroll
                for (int c = 0; c < 4; ++c) acc[r][c] = 0.0f;
            for (int p = 0; p < MO; ++p) {
                float a0 = s.Kw[ti][p], a1 = s.Kw[ti+32][p];
                float b0 = s.Pzc[p][tj],    b1 = s.Pzc[p][tj+8];
                float b2 = s.Pzc[p][tj+16], b3 = s.Pzc[p][tj+24];
                acc[0][0] += a0*b0; acc[0][1] += a0*b1; acc[0][2] += a0*b2; acc[0][3] += a0*b3;
                acc[1][0] += a1*b0; acc[1][1] += a1*b1; acc[1][2] += a1*b2; acc[1][3] += a1*b3;
            }
            #pragma unroll
            for (int r = 0; r < 2; ++r)
                #pragma unroll
                for (int c = 0; c < 4; ++c)
                    s.Mw[ti + 32*r][tj + 8*c] = acc[r][c];
        }
        __syncthreads();

        // ---- phase 15: P_new = P_pred - M K^T into L (4x4 tiles) ----
        {
            int ti = tid & 15, tj = tid >> 4;
            float acc[4][4];
            #pragma unroll
            for (int r = 0; r < 4; ++r)
                #pragma unroll
                for (int c = 0; c < 4; ++c) acc[r][c] = 0.0f;
            for (int m2 = 0; m2 < MO; ++m2) {
                float a0 = s.Mw[ti][m2],    a1 = s.Mw[ti+16][m2];
                float a2 = s.Mw[ti+32][m2], a3 = s.Mw[ti+48][m2];
                float b0 = s.Kw[tj][m2],    b1 = s.Kw[tj+16][m2];
                float b2 = s.Kw[tj+32][m2], b3 = s.Kw[tj+48][m2];
                acc[0][0] += a0*b0; acc[0][1] += a0*b1; acc[0][2] += a0*b2; acc[0][3] += a0*b3;
                acc[1][0] += a1*b0; acc[1][1] += a1*b1; acc[1][2] += a1*b2; acc[1][3] += a1*b3;
                acc[2][0] += a2*b0; acc[2][1] += a2*b1; acc[2][2] += a2*b2; acc[2][3] += a2*b3;
                acc[3][0] += a3*b0; acc[3][1] += a3*b1; acc[3][2] += a3*b2; acc[3][3] += a3*b3;
            }
            #pragma unroll
            for (int r = 0; r < 4; ++r)
                #pragma unroll
                for (int c = 0; c < 4; ++c) {
                    int i = ti + 16*r, j = tj + 16*c;
                    s.L[i][j] = s.P[i][j] - acc[r][c];
                }
        }
        __syncthreads();

        // ---- phase 16: symmetrize into P, optionally write Ps ----
        for (int idx = tid; idx < NS*NS; idx += 256) {
            int i = idx >> 6, j = idx & 63;
            float v = 0.5f * (s.L[i][j] + s.L[j][i]);
            s.P[i][j] = v;
            if (write_ps)
                out[XS_OFF + (((size_t)traj * TSTEPS + t) << 12) + idx] = v;
        }
        __syncthreads();
    }

    // ---- per-trajectory MSE ----
    if (tid < NS) s.red[tid] = mse_acc; else s.red[tid] = 0.0f;
    __syncthreads();
    if (tid == 0) {
        float tot = 0.0f;
        for (int i = 0; i < NS; ++i) tot += s.red[i];
        g_mse[traj] = tot * (1.0f / (float)(TSTEPS * NS));
    }
}

__global__ void finalize_kernel(float* __restrict__ out, unsigned long long out_size)
{
    __shared__ float sh[NTRAJ];
    int tid = threadIdx.x;
    sh[tid] = g_mse[tid];
    __syncthreads();
    if (tid == 0) {
        float tot = 0.0f;
        for (int i = 0; i < NTRAJ; ++i) tot += sh[i];
        float lin = tot / (float)NTRAJ;
        float db = 10.0f * log10f(lin);
        const unsigned long long XS = XS_OFF, PS = PS_SZ;
        if (out_size >= XS + PS + 2ULL) { out[XS+PS] = lin; out[XS+PS+1ULL] = db; }
        else if (out_size == XS + 2ULL) { out[XS] = lin; out[XS+1ULL] = db; }
        else if (out_size == 2ULL)      { out[0] = lin; out[1] = db; }
        else if (out_size == 1ULL)      { out[0] = db; }
    }
}

extern "C" void kernel_launch(void* const* d_in, const int* in_sizes, int n_in,
                              void* d_out, int out_size)
{
    const float* X = (const float*)d_in[0];
    const float* Y = (const float*)d_in[1];
    const float* F = (const float*)d_in[2];
    const float* H = (const float*)d_in[3];
    const float* Q = (const float*)d_in[4];
    const float* R = (const float*)d_in[5];
    float* out = (float*)d_out;

    unsigned long long os = (unsigned long long)(long long)out_size;
    int wxs = (os >= XS_OFF) ? 1 : 0;
    int wps = (os >= XS_OFF + PS_SZ) ? 1 : 0;

    cudaFuncSetAttribute(ukf_kernel, cudaFuncAttributeMaxDynamicSharedMemorySize,
                         (int)sizeof(SM));
    ukf_kernel<<<NTRAJ, 256, sizeof(SM)>>>(X, Y, F, H, Q, R, out, wxs, wps);
    finalize_kernel<<<1, NTRAJ>>>(out, os);
}

// round 3
// speedup vs baseline: 1.4530x; 1.4517x over previous
#include <cuda_runtime.h>
#include <cstdint>
#include <cstddef>

#define NS 64
#define MO 32
#define NSIG 129
#define TSTEPS 250
#define NTRAJ 128
#define DTC 0.02f
#define NLAM 63.0f
#define CW (0.5f/63.0f)
#define WM0 (-1.0f/63.0f)
#define WC0 (2.0f - 1.0f/63.0f)
#define WDIFF (WC0 - CW)
#define XS_OFF 2048000ULL
#define PS_SZ  131072000ULL

typedef unsigned long long ull;

__device__ __forceinline__ void fma2(ull &d, ull a, ull b) {
    asm("fma.rn.f32x2 %0, %1, %2, %0;" : "+l"(d) : "l"(a), "l"(b));
}
__device__ __forceinline__ float hsum2(ull v) {
    return __uint_as_float((unsigned)v) + __uint_as_float((unsigned)(v >> 32));
}
__device__ __forceinline__ ull ld2s(const float* p) { return *reinterpret_cast<const ull*>(p); }
__device__ __forceinline__ void st2s(float* p, ull v) { *reinterpret_cast<ull*>(p) = v; }
__device__ __forceinline__ ull pk2(float x) {
    ull r; asm("mov.b64 %0, {%1, %1};" : "=l"(r) : "f"(x)); return r;
}

struct SM {
    float F[NS][66];
    float H[MO][66];
    float P[NS][66];
    float Achol[NS][66];   // column-major working matrix: Achol[j][i]
    float Lc[NS][66];      // Lc[j][d] = L[d][j] (column j contiguous in d)
    union {
        struct { float sig[132][66]; float sf[132][66]; } u;
        float dxT[NS][130];   // 8320 floats < sig's 8712 -> no overlap with sf
    } A;
    float zs[132][34];
    float dzT[MO][130];
    float Pz[MO][33];      // Pz; chol L in-place (lower)
    float Pxz[NS][34];
    float Usm[NS][34];     // Usm[i][m] = U[m][i]
    float x[NS], xp[NS], zp[MO], innov[MO], zinv[MO], wsol[MO];
};

__device__ float g_mse[NTRAJ];

__global__ __launch_bounds__(256, 1)
void ukf_kernel(const float* __restrict__ gX, const float* __restrict__ gY,
                const float* __restrict__ gF, const float* __restrict__ gH,
                const float* __restrict__ gQ, const float* __restrict__ gR,
                float* __restrict__ out, int write_xs, int write_ps)
{
    extern __shared__ unsigned char smem_raw[];
    SM& s = *reinterpret_cast<SM*>(smem_raw);
    const int tid = threadIdx.x;
    const int traj = blockIdx.x;
    float (*sig)[66] = s.A.u.sig;
    float (*sf)[66]  = s.A.u.sf;

    // ---- init ----
    for (int idx = tid; idx < NS*NS; idx += 256) {
        int i = idx >> 6, j = idx & 63;
        s.F[i][j] = gF[idx];
        s.Achol[j][i] = (i == j) ? NLAM * (1e-5f + 1e-8f) : 0.0f;
    }
    for (int idx = tid; idx < MO*NS; idx += 256) {
        int i = idx >> 6, j = idx & 63;
        s.H[i][j] = gH[idx];
    }
    if (tid < NS) s.x[tid] = 0.0f;
    for (int idx = tid; idx < 3*66; idx += 256)        // zero sigma pad rows 129..131
        sig[NSIG + idx/66][idx%66] = 0.0f;
    float mse_acc = 0.0f;

    for (int t = 0; t < TSTEPS; ++t) {
        // ======== Cholesky-64, right-looking, 1 barrier/column ========
        {
            const int kk = tid & 63, pp = tid >> 6;
            for (int j = 0; j < NS; ++j) {
                __syncthreads();
                float ajj = s.Achol[j][j];
                float d = sqrtf(ajj);
                if (tid < NS)
                    s.Lc[j][tid] = (tid >= j) ? s.Achol[j][tid] / d : 0.0f;
                if (kk > j) {
                    ull cn = pk2(-(s.Achol[j][kk] / ajj));
                    #pragma unroll
                    for (int p = pp; p < 32; p += 4) {
                        ull av  = ld2s(&s.Achol[j][2*p]);
                        ull cur = ld2s(&s.Achol[kk][2*p]);
                        fma2(cur, av, cn);
                        st2s(&s.Achol[kk][2*p], cur);
                    }
                }
            }
        }
        __syncthreads();

        // ======== sigma points ========
        for (int idx = tid; idx < NSIG*NS; idx += 256) {
            int ss = idx >> 6, d = idx & 63;
            float v = s.x[d];
            if (ss >= 1) {
                if (ss <= NS) v += s.Lc[ss-1][d];
                else          v -= s.Lc[ss-1-NS][d];
            }
            sig[ss][d] = v;
        }
        __syncthreads();

        // ======== propagate: sf = sig + DT*tanh(sig @ F^T) ========
        for (int tt = tid; tt < 33*16; tt += 256) {
            int sq = tt >> 4, q = tt & 15, s0 = sq * 4;
            ull acc[4][4];
            #pragma unroll
            for (int r = 0; r < 4; ++r)
                #pragma unroll
                for (int c = 0; c < 4; ++c) acc[r][c] = 0ULL;
            #pragma unroll 4
            for (int kp = 0; kp < 32; ++kp) {
                ull f0 = ld2s(&s.F[q   ][2*kp]);
                ull f1 = ld2s(&s.F[q+16][2*kp]);
                ull f2 = ld2s(&s.F[q+32][2*kp]);
                ull f3 = ld2s(&s.F[q+48][2*kp]);
                ull v0 = ld2s(&sig[s0  ][2*kp]);
                ull v1 = ld2s(&sig[s0+1][2*kp]);
                ull v2 = ld2s(&sig[s0+2][2*kp]);
                ull v3 = ld2s(&sig[s0+3][2*kp]);
                fma2(acc[0][0],v0,f0); fma2(acc[0][1],v0,f1); fma2(acc[0][2],v0,f2); fma2(acc[0][3],v0,f3);
                fma2(acc[1][0],v1,f0); fma2(acc[1][1],v1,f1); fma2(acc[1][2],v1,f2); fma2(acc[1][3],v1,f3);
                fma2(acc[2][0],v2,f0); fma2(acc[2][1],v2,f1); fma2(acc[2][2],v2,f2); fma2(acc[2][3],v2,f3);
                fma2(acc[3][0],v3,f0); fma2(acc[3][1],v3,f1); fma2(acc[3][2],v3,f2); fma2(acc[3][3],v3,f3);
            }
            #pragma unroll
            for (int r = 0; r < 4; ++r)
                #pragma unroll
                for (int c = 0; c < 4; ++c) {
                    int d = q + 16*c;
                    sf[s0+r][d] = sig[s0+r][d] + DTC * tanhf(hsum2(acc[r][c]));
                }
        }
        __syncthreads();

        // ======== zs = sf @ H^T ========
        for (int tt = tid; tt < 33*8; tt += 256) {
            int sq = tt >> 3, q = tt & 7, s0 = sq * 4;
            ull acc[4][4];
            #pragma unroll
            for (int r = 0; r < 4; ++r)
                #pragma unroll
                for (int c = 0; c < 4; ++c) acc[r][c] = 0ULL;
            #pragma unroll 4
            for (int kp = 0; kp < 32; ++kp) {
                ull h0 = ld2s(&s.H[q   ][2*kp]);
                ull h1 = ld2s(&s.H[q+ 8][2*kp]);
                ull h2 = ld2s(&s.H[q+16][2*kp]);
                ull h3 = ld2s(&s.H[q+24][2*kp]);
                ull v0 = ld2s(&sf[s0  ][2*kp]);
                ull v1 = ld2s(&sf[s0+1][2*kp]);
                ull v2 = ld2s(&sf[s0+2][2*kp]);
                ull v3 = ld2s(&sf[s0+3][2*kp]);
                fma2(acc[0][0],v0,h0); fma2(acc[0][1],v0,h1); fma2(acc[0][2],v0,h2); fma2(acc[0][3],v0,h3);
                fma2(acc[1][0],v1,h0); fma2(acc[1][1],v1,h1); fma2(acc[1][2],v1,h2); fma2(acc[1][3],v1,h3);
                fma2(acc[2][0],v2,h0); fma2(acc[2][1],v2,h1); fma2(acc[2][2],v2,h2); fma2(acc[2][3],v2,h3);
                fma2(acc[3][0],v3,h0); fma2(acc[3][1],v3,h1); fma2(acc[3][2],v3,h2); fma2(acc[3][3],v3,h3);
            }
            #pragma unroll
            for (int r = 0; r < 4; ++r)
                #pragma unroll
                for (int c = 0; c < 4; ++c)
                    s.zs[s0+r][q + 8*c] = hsum2(acc[r][c]);
        }
        __syncthreads();

        // ======== means ========
        if (tid < NS) {
            float a0 = WM0 * sf[0][tid];
            float t1=0.f,t2=0.f,t3=0.f,t4=0.f;
            for (int k = 1; k + 3 < NSIG; k += 4) {
                t1 += sf[k][tid]; t2 += sf[k+1][tid]; t3 += sf[k+2][tid]; t4 += sf[k+3][tid];
            }
            s.xp[tid] = a0 + CW * ((t1+t2)+(t3+t4));
        } else if (tid < NS + MO) {
            int m = tid - NS;
            float a0 = WM0 * s.zs[0][m];
            float t1=0.f,t2=0.f,t3=0.f,t4=0.f;
            for (int k = 1; k + 3 < NSIG; k += 4) {
                t1 += s.zs[k][m]; t2 += s.zs[k+1][m]; t3 += s.zs[k+2][m]; t4 += s.zs[k+3][m];
            }
            s.zp[m] = a0 + CW * ((t1+t2)+(t3+t4));
        }
        __syncthreads();

        // ======== deltas (transposed) + innovation ========
        {
            int d = tid & 63, c = tid >> 6;
            float xv = s.xp[d];
            for (int k = c; k < NSIG; k += 4) s.A.dxT[d][k] = sf[k][d] - xv;
        }
        {
            int m = tid & 31, c = tid >> 5;
            float zv = s.zp[m];
            for (int k = c; k < NSIG; k += 8) s.dzT[m][k] = s.zs[k][m] - zv;
        }
        if (tid >= 224) {
            int m = tid - 224;
            s.innov[m] = gY[(size_t)traj * TSTEPS * MO + (size_t)t * MO + m] - s.zp[m];
        }
        __syncthreads();

        // ======== Pz gram (all 256 threads, 2x2 tiles) ========
        {
            int ti = tid & 15, tj = tid >> 4;
            ull acc[2][2] = {{0ULL,0ULL},{0ULL,0ULL}};
            #pragma unroll 4
            for (int kp = 0; kp < 64; ++kp) {
                ull a0 = ld2s(&s.dzT[ti   ][2*kp]);
                ull a1 = ld2s(&s.dzT[ti+16][2*kp]);
                ull b0 = ld2s(&s.dzT[tj   ][2*kp]);
                ull b1 = ld2s(&s.dzT[tj+16][2*kp]);
                fma2(acc[0][0],a0,b0); fma2(acc[0][1],a0,b1);
                fma2(acc[1][0],a1,b0); fma2(acc[1][1],a1,b1);
            }
            float ap0=s.dzT[ti][128], ap1=s.dzT[ti+16][128];
            float bp0=s.dzT[tj][128], bp1=s.dzT[tj+16][128];
            float a00=s.dzT[ti][0],   a01=s.dzT[ti+16][0];
            float b00=s.dzT[tj][0],   b01=s.dzT[tj+16][0];
            s.Pz[ti   ][tj   ] = CW*(hsum2(acc[0][0])+ap0*bp0) + WDIFF*a00*b00 + gR[ ti     *MO + tj   ];
            s.Pz[ti   ][tj+16] = CW*(hsum2(acc[0][1])+ap0*bp1) + WDIFF*a00*b01 + gR[ ti     *MO + tj+16];
            s.Pz[ti+16][tj   ] = CW*(hsum2(acc[1][0])+ap1*bp0) + WDIFF*a01*b00 + gR[(ti+16)*MO + tj   ];
            s.Pz[ti+16][tj+16] = CW*(hsum2(acc[1][1])+ap1*bp1) + WDIFF*a01*b01 + gR[(ti+16)*MO + tj+16];
        }
        __syncthreads();

        // ======== warp0: chol32 of Pz  |  threads 32..255: P_pred + Pxz grams ========
        if (tid < 32) {
            int lane = tid;
            for (int j = 0; j < MO; ++j) {
                float c = 0.0f;
                if (lane >= j) {
                    c = s.Pz[lane][j];
                    float c0=0.f, c1=0.f; int k = 0;
                    for (; k + 1 < j; k += 2) {
                        c0 += s.Pz[lane][k]   * s.Pz[j][k];
                        c1 += s.Pz[lane][k+1] * s.Pz[j][k+1];
                    }
                    if (k < j) c0 += s.Pz[lane][k] * s.Pz[j][k];
                    c -= c0 + c1;
                }
                float cj = __shfl_sync(0xffffffffu, c, j);
                float d = sqrtf(cj);
                if (lane == j)      { s.Pz[j][j] = d; s.zinv[j] = 1.0f / d; }
                else if (lane > j)  { s.Pz[lane][j] = c / d; }
                __syncwarp();
            }
        } else {
            for (int idx = tid - 32; idx < 384; idx += 224) {
                if (idx < 256) {
                    // P_pred 4x4 tile
                    int ti = idx & 15, tj = idx >> 4;
                    ull acc[4][4];
                    #pragma unroll
                    for (int r = 0; r < 4; ++r)
                        #pragma unroll
                        for (int c = 0; c < 4; ++c) acc[r][c] = 0ULL;
                    #pragma unroll 4
                    for (int kp = 0; kp < 64; ++kp) {
                        ull a0 = ld2s(&s.A.dxT[ti   ][2*kp]);
                        ull a1 = ld2s(&s.A.dxT[ti+16][2*kp]);
                        ull a2 = ld2s(&s.A.dxT[ti+32][2*kp]);
                        ull a3 = ld2s(&s.A.dxT[ti+48][2*kp]);
                        ull b0 = ld2s(&s.A.dxT[tj   ][2*kp]);
                        ull b1 = ld2s(&s.A.dxT[tj+16][2*kp]);
                        ull b2 = ld2s(&s.A.dxT[tj+32][2*kp]);
                        ull b3 = ld2s(&s.A.dxT[tj+48][2*kp]);
                        fma2(acc[0][0],a0,b0); fma2(acc[0][1],a0,b1); fma2(acc[0][2],a0,b2); fma2(acc[0][3],a0,b3);
                        fma2(acc[1][0],a1,b0); fma2(acc[1][1],a1,b1); fma2(acc[1][2],a1,b2); fma2(acc[1][3],a1,b3);
                        fma2(acc[2][0],a2,b0); fma2(acc[2][1],a2,b1); fma2(acc[2][2],a2,b2); fma2(acc[2][3],a2,b3);
                        fma2(acc[3][0],a3,b0); fma2(acc[3][1],a3,b1); fma2(acc[3][2],a3,b2); fma2(acc[3][3],a3,b3);
                    }
                    #pragma unroll
                    for (int r = 0; r < 4; ++r)
                        #pragma unroll
                        for (int c = 0; c < 4; ++c) {
                            int i = ti + 16*r, j = tj + 16*c;
                            float sm = hsum2(acc[r][c]) + s.A.dxT[i][128]*s.A.dxT[j][128];
                            s.P[i][j] = CW*sm + WDIFF * s.A.dxT[i][0]*s.A.dxT[j][0] + gQ[i*NS + j];
                        }
                } else {
                    // Pxz 4x4 tile
                    int q = idx - 256, ti = q & 15, tj = q >> 4;
                    ull acc[4][4];
                    #pragma unroll
                    for (int r = 0; r < 4; ++r)
                        #pragma unroll
                        for (int c = 0; c < 4; ++c) acc[r][c] = 0ULL;
                    #pragma unroll 4
                    for (int kp = 0; kp < 64; ++kp) {
                        ull a0 = ld2s(&s.A.dxT[ti   ][2*kp]);
                        ull a1 = ld2s(&s.A.dxT[ti+16][2*kp]);
                        ull a2 = ld2s(&s.A.dxT[ti+32][2*kp]);
                        ull a3 = ld2s(&s.A.dxT[ti+48][2*kp]);
                        ull b0 = ld2s(&s.dzT[tj   ][2*kp]);
                        ull b1 = ld2s(&s.dzT[tj+ 8][2*kp]);
                        ull b2 = ld2s(&s.dzT[tj+16][2*kp]);
                        ull b3 = ld2s(&s.dzT[tj+24][2*kp]);
                        fma2(acc[0][0],a0,b0); fma2(acc[0][1],a0,b1); fma2(acc[0][2],a0,b2); fma2(acc[0][3],a0,b3);
                        fma2(acc[1][0],a1,b0); fma2(acc[1][1],a1,b1); fma2(acc[1][2],a1,b2); fma2(acc[1][3],a1,b3);
                        fma2(acc[2][0],a2,b0); fma2(acc[2][1],a2,b1); fma2(acc[2][2],a2,b2); fma2(acc[2][3],a2,b3);
                        fma2(acc[3][0],a3,b0); fma2(acc[3][1],a3,b1); fma2(acc[3][2],a3,b2); fma2(acc[3][3],a3,b3);
                    }
                    #pragma unroll
                    for (int r = 0; r < 4; ++r)
                        #pragma unroll
                        for (int c = 0; c < 4; ++c) {
                            int i = ti + 16*r, m = tj + 8*c;
                            float sm = hsum2(acc[r][c]) + s.A.dxT[i][128]*s.dzT[m][128];
                            s.Pxz[i][m] = CW*sm + WDIFF * s.A.dxT[i][0]*s.dzT[m][0];
                        }
                }
            }
        }
        __syncthreads();

        // ======== forward solves: L * [U | w] = [Pxz^T | innov] ========
        if (tid < NS + 1) {
            float v[MO];
            if (tid < NS) {
                #pragma unroll
                for (int m = 0; m < MO; ++m) v[m] = s.Pxz[tid][m];
            } else {
                #pragma unroll
                for (int m = 0; m < MO; ++m) v[m] = s.innov[m];
            }
            #pragma unroll
            for (int i = 0; i < MO; ++i) {
                float acc = v[i];
                #pragma unroll
                for (int j = 0; j < i; ++j) acc -= s.Pz[i][j] * v[j];
                v[i] = acc * s.zinv[i];
            }
            if (tid < NS) {
                #pragma unroll
                for (int m = 0; m < MO; ++m) s.Usm[tid][m] = v[m];
            } else {
                #pragma unroll
                for (int m = 0; m < MO; ++m) s.wsol[m] = v[m];
            }
        }
        __syncthreads();

        // ======== x_new (tid<64) ========
        if (tid < NS) {
            float xn = s.xp[tid];
            #pragma unroll
            for (int m = 0; m < MO; ++m) xn += s.Usm[tid][m] * s.wsol[m];
            s.x[tid] = xn;
            size_t oidx = ((size_t)traj * TSTEPS + t) * NS + tid;
            if (write_xs) out[oidx] = xn;
            float de = xn - gX[oidx];
            mse_acc += de * de;
        }

        // ======== P_new = P_pred - U^T U; build next Achol (all 256) ========
        {
            int ti = tid & 15, tj = tid >> 4;
            ull acc[4][4];
            #pragma unroll
            for (int r = 0; r < 4; ++r)
                #pragma unroll
                for (int c = 0; c < 4; ++c) acc[r][c] = 0ULL;
            #pragma unroll
            for (int mp = 0; mp < 16; ++mp) {
                ull a0 = ld2s(&s.Usm[ti   ][2*mp]);
                ull a1 = ld2s(&s.Usm[ti+16][2*mp]);
                ull a2 = ld2s(&s.Usm[ti+32][2*mp]);
                ull a3 = ld2s(&s.Usm[ti+48][2*mp]);
                ull b0 = ld2s(&s.Usm[tj   ][2*mp]);
                ull b1 = ld2s(&s.Usm[tj+16][2*mp]);
                ull b2 = ld2s(&s.Usm[tj+32][2*mp]);
                ull b3 = ld2s(&s.Usm[tj+48][2*mp]);
                fma2(acc[0][0],a0,b0); fma2(acc[0][1],a0,b1); fma2(acc[0][2],a0,b2); fma2(acc[0][3],a0,b3);
                fma2(acc[1][0],a1,b0); fma2(acc[1][1],a1,b1); fma2(acc[1][2],a1,b2); fma2(acc[1][3],a1,b3);
                fma2(acc[2][0],a2,b0); fma2(acc[2][1],a2,b1); fma2(acc[2][2],a2,b2); fma2(acc[2][3],a2,b3);
                fma2(acc[3][0],a3,b0); fma2(acc[3][1],a3,b1); fma2(acc[3][2],a3,b2); fma2(acc[3][3],a3,b3);
            }
            #pragma unroll
            for (int r = 0; r < 4; ++r)
                #pragma unroll
                for (int c = 0; c < 4; ++c) {
                    int i = ti + 16*r, j = tj + 16*c;
                    float pv = s.P[i][j] - hsum2(acc[r][c]);
                    s.Achol[j][i] = NLAM * (pv + ((i == j) ? 1e-8f : 0.0f));
                    if (write_ps)
                        out[XS_OFF + (((size_t)traj * TSTEPS + t) << 12) + (size_t)i*NS + j] = pv;
                }
        }
        __syncthreads();
    }

    // ---- per-trajectory MSE ----
    {
        // reduce mse_acc over threads 0..63 via shuffles within warps then smem
        __shared__ float red[8];
        float v = (tid < NS) ? mse_acc : 0.0f;
        for (int o = 16; o > 0; o >>= 1) v += __shfl_down_sync(0xffffffffu, v, o);
        if ((tid & 31) == 0) red[tid >> 5] = v;
        __syncthreads();
        if (tid == 0) {
            float tot = red[0] + red[1];   // only warps 0,1 hold tid<64
            g_mse[traj] = tot * (1.0f / (float)(TSTEPS * NS));
        }
    }
}

__global__ void finalize_kernel(float* __restrict__ out, unsigned long long out_size)
{
    __shared__ float sh[NTRAJ];
    int tid = threadIdx.x;
    sh[tid] = g_mse[tid];
    __syncthreads();
    if (tid == 0) {
        float tot = 0.0f;
        for (int i = 0; i < NTRAJ; ++i) tot += sh[i];
        float lin = tot / (float)NTRAJ;
        float db = 10.0f * log10f(lin);
        const unsigned long long XS = XS_OFF, PS = PS_SZ;
        if (out_size >= XS + PS + 2ULL) { out[XS+PS] = lin; out[XS+PS+1ULL] = db; }
        else if (out_size == XS + 2ULL) { out[XS] = lin; out[XS+1ULL] = db; }
        else if (out_size == 2ULL)      { out[0] = lin; out[1] = db; }
        else if (out_size == 1ULL)      { out[0] = db; }
    }
}

extern "C" void kernel_launch(void* const* d_in, const int* in_sizes, int n_in,
                              void* d_out, int out_size)
{
    const float* X = (const float*)d_in[0];
    const float* Y = (const float*)d_in[1];
    const float* F = (const float*)d_in[2];
    const float* H = (const float*)d_in[3];
    const float* Q = (const float*)d_in[4];
    const float* R = (const float*)d_in[5];
    float* out = (float*)d_out;

    unsigned long long os = (unsigned long long)(long long)out_size;
    int wxs = (os >= XS_OFF) ? 1 : 0;
    int wps = (os >= XS_OFF + PS_SZ) ? 1 : 0;

    cudaFuncSetAttribute(ukf_kernel, cudaFuncAttributeMaxDynamicSharedMemorySize,
                         (int)sizeof(SM));
    ukf_kernel<<<NTRAJ, 256, sizeof(SM)>>>(X, Y, F, H, Q, R, out, wxs, wps);
    finalize_kernel<<<1, NTRAJ>>>(out, os);
}

// round 4
// speedup vs baseline: 1.4979x; 1.0309x over previous
#include <cuda_runtime.h>
#include <cstdint>
#include <cstddef>

#define NS 64
#define MO 32
#define NSIG 129
#define TSTEPS 250
#define NTRAJ 128
#define DTC 0.02f
#define NLAM 63.0f
#define CW (0.5f/63.0f)
#define WM0 (-1.0f/63.0f)
#define WC0 (2.0f - 1.0f/63.0f)
#define WDIFF (WC0 - CW)
#define WMD (WM0 - CW)
#define XS_OFF 2048000ULL
#define PS_SZ  131072000ULL

typedef unsigned long long ull;

__device__ __forceinline__ void fma2(ull &d, ull a, ull b) {
    asm("fma.rn.f32x2 %0, %1, %2, %0;" : "+l"(d) : "l"(a), "l"(b));
}
__device__ __forceinline__ float hsum2(ull v) {
    return __uint_as_float((unsigned)v) + __uint_as_float((unsigned)(v >> 32));
}
__device__ __forceinline__ ull ld2s(const float* p) { return *reinterpret_cast<const ull*>(p); }
__device__ __forceinline__ void st2s(float* p, ull v) { *reinterpret_cast<ull*>(p) = v; }
__device__ __forceinline__ ull pk2(float x) {
    ull r; asm("mov.b64 %0, {%1, %1};" : "=l"(r) : "f"(x)); return r;
}
__device__ __forceinline__ float tanh_fast(float x) {
    float r; asm("tanh.approx.f32 %0, %1;" : "=f"(r) : "f"(x)); return r;
}

struct SM {
    float F[NS][66];
    float H[MO][66];
    float P[NS][66];
    float Achol[NS][66];   // column-major: Achol[j][i]
    float Lc[NS][66];      // Lc[k][d] = L[d][k]
    float sf[132][66];
    union { float Gk[NS][66]; float dxT[NS][130]; } A;
    float zs[132][34];
    float dzT[MO][130];
    float Pz[MO][33];
    float Pxz[NS][34];
    float Usm[NS][34];
    float pmean[4][66];
    float zmean[8][34];
    float row0[NS];
    float x[NS], xp[NS], zp[MO], innov[MO], zinv[MO], wsol[MO];
    float red[8];
};

__device__ float g_mse[NTRAJ];
__device__ unsigned int g_ctr = 0;

__global__ __launch_bounds__(256, 1)
void ukf_kernel(const float* __restrict__ gX, const float* __restrict__ gY,
                const float* __restrict__ gF, const float* __restrict__ gH,
                const float* __restrict__ gQ, const float* __restrict__ gR,
                float* __restrict__ out, int write_xs, int write_ps,
                unsigned long long osz)
{
    extern __shared__ unsigned char smem_raw[];
    SM& s = *reinterpret_cast<SM*>(smem_raw);
    const int tid = threadIdx.x;
    const int traj = blockIdx.x;

    // ---- init ----
    for (int idx = tid; idx < NS*NS; idx += 256) {
        int i = idx >> 6, j = idx & 63;
        s.F[i][j] = gF[idx];
        s.Achol[j][i] = (i == j) ? NLAM * (1e-5f + 1e-8f) : 0.0f;
    }
    for (int idx = tid; idx < MO*NS; idx += 256) {
        int i = idx >> 6, j = idx & 63;
        s.H[i][j] = gH[idx];
    }
    if (tid < NS) s.x[tid] = 0.0f;
    for (int idx = tid; idx < 3*66; idx += 256)   // sf pad rows 129..131 -> 0
        s.sf[NSIG + idx/66][idx%66] = 0.0f;
    float mse_acc = 0.0f;

    for (int t = 0; t < TSTEPS; ++t) {
        // ======== Cholesky-64, right-looking, 1 barrier/column ========
        {
            const int kk = tid & 63, pp = tid >> 6;
            for (int j = 0; j < NS; ++j) {
                __syncthreads();
                float ajj = s.Achol[j][j];
                float d = sqrtf(ajj);
                if (tid < NS)
                    s.Lc[j][tid] = (tid >= j) ? s.Achol[j][tid] / d : 0.0f;
                if (kk > j) {
                    ull cn = pk2(-(s.Achol[j][kk] / ajj));
                    #pragma unroll
                    for (int p = pp; p < 32; p += 4) {
                        ull av  = ld2s(&s.Achol[j][2*p]);
                        ull cur = ld2s(&s.Achol[kk][2*p]);
                        fma2(cur, av, cn);
                        st2s(&s.Achol[kk][2*p], cur);
                    }
                }
            }
        }
        __syncthreads();

        // ======== Gk = Lc @ F^T (Gk[k][d] = sum_e Lc[k][e]*F[d][e]); row0 on tid<64 ========
        {
            int tk = tid & 15, td = tid >> 4;
            ull acc[4][4];
            #pragma unroll
            for (int r = 0; r < 4; ++r)
                #pragma unroll
                for (int c = 0; c < 4; ++c) acc[r][c] = 0ULL;
            #pragma unroll 2
            for (int kp = 0; kp < 32; ++kp) {
                ull a0 = ld2s(&s.Lc[tk   ][2*kp]);
                ull a1 = ld2s(&s.Lc[tk+16][2*kp]);
                ull a2 = ld2s(&s.Lc[tk+32][2*kp]);
                ull a3 = ld2s(&s.Lc[tk+48][2*kp]);
                ull b0 = ld2s(&s.F[td   ][2*kp]);
                ull b1 = ld2s(&s.F[td+16][2*kp]);
                ull b2 = ld2s(&s.F[td+32][2*kp]);
                ull b3 = ld2s(&s.F[td+48][2*kp]);
                fma2(acc[0][0],a0,b0); fma2(acc[0][1],a0,b1); fma2(acc[0][2],a0,b2); fma2(acc[0][3],a0,b3);
                fma2(acc[1][0],a1,b0); fma2(acc[1][1],a1,b1); fma2(acc[1][2],a1,b2); fma2(acc[1][3],a1,b3);
                fma2(acc[2][0],a2,b0); fma2(acc[2][1],a2,b1); fma2(acc[2][2],a2,b2); fma2(acc[2][3],a2,b3);
                fma2(acc[3][0],a3,b0); fma2(acc[3][1],a3,b1); fma2(acc[3][2],a3,b2); fma2(acc[3][3],a3,b3);
            }
            #pragma unroll
            for (int r = 0; r < 4; ++r)
                #pragma unroll
                for (int c = 0; c < 4; ++c)
                    s.A.Gk[tk + 16*r][td + 16*c] = hsum2(acc[r][c]);
            if (tid < NS) {
                ull rc = 0ULL;
                #pragma unroll 2
                for (int kp = 0; kp < 32; ++kp)
                    fma2(rc, ld2s(&s.x[2*kp]), ld2s(&s.F[tid][2*kp]));
                s.row0[tid] = hsum2(rc);
            }
        }
        __syncthreads();

        // ======== sf: element-wise (no sigma materialization) ========
        for (int idx = tid; idx < NSIG*NS; idx += 256) {
            int r = idx >> 6, d = idx & 63;
            float base = s.x[d], arg = s.row0[d];
            if (r >= 1) {
                int k = (r <= NS) ? r - 1 : r - 1 - NS;
                float lv = s.Lc[k][d], gv = s.A.Gk[k][d];
                if (r <= NS) { base += lv; arg += gv; }
                else         { base -= lv; arg -= gv; }
            }
            s.sf[r][d] = base + DTC * tanh_fast(arg);
        }
        __syncthreads();

        // ======== zs = sf @ H^T ========
        for (int tt = tid; tt < 33*8; tt += 256) {
            int sq = tt >> 3, q = tt & 7, s0 = sq * 4;
            ull acc[4][4];
            #pragma unroll
            for (int r = 0; r < 4; ++r)
                #pragma unroll
                for (int c = 0; c < 4; ++c) acc[r][c] = 0ULL;
            #pragma unroll 2
            for (int kp = 0; kp < 32; ++kp) {
                ull h0 = ld2s(&s.H[q   ][2*kp]);
                ull h1 = ld2s(&s.H[q+ 8][2*kp]);
                ull h2 = ld2s(&s.H[q+16][2*kp]);
                ull h3 = ld2s(&s.H[q+24][2*kp]);
                ull v0 = ld2s(&s.sf[s0  ][2*kp]);
                ull v1 = ld2s(&s.sf[s0+1][2*kp]);
                ull v2 = ld2s(&s.sf[s0+2][2*kp]);
                ull v3 = ld2s(&s.sf[s0+3][2*kp]);
                fma2(acc[0][0],v0,h0); fma2(acc[0][1],v0,h1); fma2(acc[0][2],v0,h2); fma2(acc[0][3],v0,h3);
                fma2(acc[1][0],v1,h0); fma2(acc[1][1],v1,h1); fma2(acc[1][2],v1,h2); fma2(acc[1][3],v1,h3);
                fma2(acc[2][0],v2,h0); fma2(acc[2][1],v2,h1); fma2(acc[2][2],v2,h2); fma2(acc[2][3],v2,h3);
                fma2(acc[3][0],v3,h0); fma2(acc[3][1],v3,h1); fma2(acc[3][2],v3,h2); fma2(acc[3][3],v3,h3);
            }
            #pragma unroll
            for (int r = 0; r < 4; ++r)
                #pragma unroll
                for (int c = 0; c < 4; ++c)
                    s.zs[s0+r][q + 8*c] = hsum2(acc[r][c]);
        }
        __syncthreads();

        // ======== partial means (all 256 threads) ========
        {
            int d = tid & 63, g = tid >> 6;          // 4 groups of 33 (last 30)
            int k0 = g * 33, k1 = (g == 3) ? NSIG : k0 + 33;
            float t0 = 0.f, t1 = 0.f;
            int k = k0;
            for (; k + 1 < k1; k += 2) { t0 += s.sf[k][d]; t1 += s.sf[k+1][d]; }
            if (k < k1) t0 += s.sf[k][d];
            s.pmean[g][d] = t0 + t1;
        }
        {
            int m = tid & 31, g = tid >> 5;          // 8 groups of 17 (last 10)
            int k0 = g * 17, k1 = (g == 7) ? NSIG : k0 + 17;
            float t0 = 0.f, t1 = 0.f;
            int k = k0;
            for (; k + 1 < k1; k += 2) { t0 += s.zs[k][m]; t1 += s.zs[k+1][m]; }
            if (k < k1) t0 += s.zs[k][m];
            s.zmean[g][m] = t0 + t1;
        }
        __syncthreads();

        // ======== combine means + innovation ========
        if (tid < NS) {
            float S = s.pmean[0][tid] + s.pmean[1][tid] + s.pmean[2][tid] + s.pmean[3][tid];
            s.xp[tid] = CW * S + WMD * s.sf[0][tid];
        } else if (tid < NS + MO) {
            int m = tid - NS;
            float S = ((s.zmean[0][m] + s.zmean[1][m]) + (s.zmean[2][m] + s.zmean[3][m]))
                    + ((s.zmean[4][m] + s.zmean[5][m]) + (s.zmean[6][m] + s.zmean[7][m]));
            float zpv = CW * S + WMD * s.zs[0][m];
            s.zp[m] = zpv;
            s.innov[m] = gY[(size_t)traj * TSTEPS * MO + (size_t)t * MO + m] - zpv;
        }
        __syncthreads();

        // ======== deltas (transposed) ========
        {
            int d = tid & 63, c = tid >> 6;
            float xv = s.xp[d];
            for (int k = c; k < NSIG; k += 4) s.A.dxT[d][k] = s.sf[k][d] - xv;
        }
        {
            int m = tid & 31, c = tid >> 5;
            float zv = s.zp[m];
            for (int k = c; k < NSIG; k += 8) s.dzT[m][k] = s.zs[k][m] - zv;
        }
        __syncthreads();

        // ======== Pz gram (2x2 tiles, all threads) ========
        {
            int ti = tid & 15, tj = tid >> 4;
            ull acc[2][2] = {{0ULL,0ULL},{0ULL,0ULL}};
            #pragma unroll 2
            for (int kp = 0; kp < 64; ++kp) {
                ull a0 = ld2s(&s.dzT[ti   ][2*kp]);
                ull a1 = ld2s(&s.dzT[ti+16][2*kp]);
                ull b0 = ld2s(&s.dzT[tj   ][2*kp]);
                ull b1 = ld2s(&s.dzT[tj+16][2*kp]);
                fma2(acc[0][0],a0,b0); fma2(acc[0][1],a0,b1);
                fma2(acc[1][0],a1,b0); fma2(acc[1][1],a1,b1);
            }
            float ap0=s.dzT[ti][128], ap1=s.dzT[ti+16][128];
            float bp0=s.dzT[tj][128], bp1=s.dzT[tj+16][128];
            float a00=s.dzT[ti][0],   a01=s.dzT[ti+16][0];
            float b00=s.dzT[tj][0],   b01=s.dzT[tj+16][0];
            s.Pz[ti   ][tj   ] = CW*(hsum2(acc[0][0])+ap0*bp0) + WDIFF*a00*b00 + gR[ ti     *MO + tj   ];
            s.Pz[ti   ][tj+16] = CW*(hsum2(acc[0][1])+ap0*bp1) + WDIFF*a00*b01 + gR[ ti     *MO + tj+16];
            s.Pz[ti+16][tj   ] = CW*(hsum2(acc[1][0])+ap1*bp0) + WDIFF*a01*b00 + gR[(ti+16)*MO + tj   ];
            s.Pz[ti+16][tj+16] = CW*(hsum2(acc[1][1])+ap1*bp1) + WDIFF*a01*b01 + gR[(ti+16)*MO + tj+16];
        }
        __syncthreads();

        // ======== warp0: chol32(Pz)  |  tid 32..255: P_pred + Pxz grams ========
        if (tid < 32) {
            int lane = tid;
            for (int j = 0; j < MO; ++j) {
                float c = 0.0f;
                if (lane >= j) {
                    c = s.Pz[lane][j];
                    float c0=0.f, c1=0.f; int k = 0;
                    for (; k + 1 < j; k += 2) {
                        c0 += s.Pz[lane][k]   * s.Pz[j][k];
                        c1 += s.Pz[lane][k+1] * s.Pz[j][k+1];
                    }
                    if (k < j) c0 += s.Pz[lane][k] * s.Pz[j][k];
                    c -= c0 + c1;
                }
                float cj = __shfl_sync(0xffffffffu, c, j);
                float d = sqrtf(cj);
                if (lane == j)      { s.Pz[j][j] = d; s.zinv[j] = 1.0f / d; }
                else if (lane > j)  { s.Pz[lane][j] = c / d; }
                __syncwarp();
            }
        } else {
            for (int idx = tid - 32; idx < 384; idx += 224) {
                if (idx < 256) {
                    int ti = idx & 15, tj = idx >> 4;
                    ull acc[4][4];
                    #pragma unroll
                    for (int r = 0; r < 4; ++r)
                        #pragma unroll
                        for (int c = 0; c < 4; ++c) acc[r][c] = 0ULL;
                    #pragma unroll 2
                    for (int kp = 0; kp < 64; ++kp) {
                        ull a0 = ld2s(&s.A.dxT[ti   ][2*kp]);
                        ull a1 = ld2s(&s.A.dxT[ti+16][2*kp]);
                        ull a2 = ld2s(&s.A.dxT[ti+32][2*kp]);
                        ull a3 = ld2s(&s.A.dxT[ti+48][2*kp]);
                        ull b0 = ld2s(&s.A.dxT[tj   ][2*kp]);
                        ull b1 = ld2s(&s.A.dxT[tj+16][2*kp]);
                        ull b2 = ld2s(&s.A.dxT[tj+32][2*kp]);
                        ull b3 = ld2s(&s.A.dxT[tj+48][2*kp]);
                        fma2(acc[0][0],a0,b0); fma2(acc[0][1],a0,b1); fma2(acc[0][2],a0,b2); fma2(acc[0][3],a0,b3);
                        fma2(acc[1][0],a1,b0); fma2(acc[1][1],a1,b1); fma2(acc[1][2],a1,b2); fma2(acc[1][3],a1,b3);
                        fma2(acc[2][0],a2,b0); fma2(acc[2][1],a2,b1); fma2(acc[2][2],a2,b2); fma2(acc[2][3],a2,b3);
                        fma2(acc[3][0],a3,b0); fma2(acc[3][1],a3,b1); fma2(acc[3][2],a3,b2); fma2(acc[3][3],a3,b3);
                    }
                    #pragma unroll
                    for (int r = 0; r < 4; ++r)
                        #pragma unroll
                        for (int c = 0; c < 4; ++c) {
                            int i = ti + 16*r, j = tj + 16*c;
                            float sm = hsum2(acc[r][c]) + s.A.dxT[i][128]*s.A.dxT[j][128];
                            s.P[i][j] = CW*sm + WDIFF * s.A.dxT[i][0]*s.A.dxT[j][0] + gQ[i*NS + j];
                        }
                } else {
                    int q = idx - 256, ti = q & 15, tj = q >> 4;
                    ull acc[4][4];
                    #pragma unroll
                    for (int r = 0; r < 4; ++r)
                        #pragma unroll
                        for (int c = 0; c < 4; ++c) acc[r][c] = 0ULL;
                    #pragma unroll 2
                    for (int kp = 0; kp < 64; ++kp) {
                        ull a0 = ld2s(&s.A.dxT[ti   ][2*kp]);
                        ull a1 = ld2s(&s.A.dxT[ti+16][2*kp]);
                        ull a2 = ld2s(&s.A.dxT[ti+32][2*kp]);
                        ull a3 = ld2s(&s.A.dxT[ti+48][2*kp]);
                        ull b0 = ld2s(&s.dzT[tj   ][2*kp]);
                        ull b1 = ld2s(&s.dzT[tj+ 8][2*kp]);
                        ull b2 = ld2s(&s.dzT[tj+16][2*kp]);
                        ull b3 = ld2s(&s.dzT[tj+24][2*kp]);
                        fma2(acc[0][0],a0,b0); fma2(acc[0][1],a0,b1); fma2(acc[0][2],a0,b2); fma2(acc[0][3],a0,b3);
                        fma2(acc[1][0],a1,b0); fma2(acc[1][1],a1,b1); fma2(acc[1][2],a1,b2); fma2(acc[1][3],a1,b3);
                        fma2(acc[2][0],a2,b0); fma2(acc[2][1],a2,b1); fma2(acc[2][2],a2,b2); fma2(acc[2][3],a2,b3);
                        fma2(acc[3][0],a3,b0); fma2(acc[3][1],a3,b1); fma2(acc[3][2],a3,b2); fma2(acc[3][3],a3,b3);
                    }
                    #pragma unroll
                    for (int r = 0; r < 4; ++r)
                        #pragma unroll
                        for (int c = 0; c < 4; ++c) {
                            int i = ti + 16*r, m = tj + 8*c;
                            float sm = hsum2(acc[r][c]) + s.A.dxT[i][128]*s.dzT[m][128];
                            s.Pxz[i][m] = CW*sm + WDIFF * s.A.dxT[i][0]*s.dzT[m][0];
                        }
                }
            }
        }
        __syncthreads();

        // ======== forward solves: L * [U | w] = [Pxz^T | innov] ========
        if (tid < NS + 1) {
            float v[MO];
            if (tid < NS) {
                #pragma unroll
                for (int m = 0; m < MO; ++m) v[m] = s.Pxz[tid][m];
            } else {
                #pragma unroll
                for (int m = 0; m < MO; ++m) v[m] = s.innov[m];
            }
            #pragma unroll
            for (int i = 0; i < MO; ++i) {
                float acc = v[i];
                #pragma unroll
                for (int j = 0; j < i; ++j) acc -= s.Pz[i][j] * v[j];
                v[i] = acc * s.zinv[i];
            }
            if (tid < NS) {
                #pragma unroll
                for (int m = 0; m < MO; ++m) s.Usm[tid][m] = v[m];
            } else {
                #pragma unroll
                for (int m = 0; m < MO; ++m) s.wsol[m] = v[m];
            }
        }
        __syncthreads();

        // ======== x_new ========
        if (tid < NS) {
            float xn = s.xp[tid];
            #pragma unroll
            for (int m = 0; m < MO; ++m) xn += s.Usm[tid][m] * s.wsol[m];
            s.x[tid] = xn;
            size_t oidx = ((size_t)traj * TSTEPS + t) * NS + tid;
            if (write_xs) out[oidx] = xn;
            float de = xn - gX[oidx];
            mse_acc += de * de;
        }

        // ======== P_new = P_pred - U^T U; build next Achol ========
        {
            int ti = tid & 15, tj = tid >> 4;
            ull acc[4][4];
            #pragma unroll
            for (int r = 0; r < 4; ++r)
                #pragma unroll
                for (int c = 0; c < 4; ++c) acc[r][c] = 0ULL;
            #pragma unroll 2
            for (int mp = 0; mp < 16; ++mp) {
                ull a0 = ld2s(&s.Usm[ti   ][2*mp]);
                ull a1 = ld2s(&s.Usm[ti+16][2*mp]);
                ull a2 = ld2s(&s.Usm[ti+32][2*mp]);
                ull a3 = ld2s(&s.Usm[ti+48][2*mp]);
                ull b0 = ld2s(&s.Usm[tj   ][2*mp]);
                ull b1 = ld2s(&s.Usm[tj+16][2*mp]);
                ull b2 = ld2s(&s.Usm[tj+32][2*mp]);
                ull b3 = ld2s(&s.Usm[tj+48][2*mp]);
                fma2(acc[0][0],a0,b0); fma2(acc[0][1],a0,b1); fma2(acc[0][2],a0,b2); fma2(acc[0][3],a0,b3);
                fma2(acc[1][0],a1,b0); fma2(acc[1][1],a1,b1); fma2(acc[1][2],a1,b2); fma2(acc[1][3],a1,b3);
                fma2(acc[2][0],a2,b0); fma2(acc[2][1],a2,b1); fma2(acc[2][2],a2,b2); fma2(acc[2][3],a2,b3);
                fma2(acc[3][0],a3,b0); fma2(acc[3][1],a3,b1); fma2(acc[3][2],a3,b2); fma2(acc[3][3],a3,b3);
            }
            #pragma unroll
            for (int r = 0; r < 4; ++r)
                #pragma unroll
                for (int c = 0; c < 4; ++c) {
                    int i = ti + 16*r, j = tj + 16*c;
                    float pv = s.P[i][j] - hsum2(acc[r][c]);
                    s.Achol[j][i] = NLAM * (pv + ((i == j) ? 1e-8f : 0.0f));
                    if (write_ps)
                        out[XS_OFF + (((size_t)traj * TSTEPS + t) << 12) + (size_t)i*NS + j] = pv;
                }
        }
        __syncthreads();
    }

    // ---- per-trajectory MSE + merged finalize ----
    {
        float v = (tid < NS) ? mse_acc : 0.0f;
        for (int o = 16; o > 0; o >>= 1) v += __shfl_down_sync(0xffffffffu, v, o);
        if ((tid & 31) == 0) s.red[tid >> 5] = v;
        __syncthreads();
        if (tid == 0) {
            g_mse[traj] = (s.red[0] + s.red[1]) * (1.0f / (float)(TSTEPS * NS));
            __threadfence();
            unsigned int prev = atomicAdd(&g_ctr, 1u);
            if (prev == NTRAJ - 1) {
                __threadfence();
                float tot = 0.0f;
                for (int i = 0; i < NTRAJ; ++i) tot += g_mse[i];
                float lin = tot / (float)NTRAJ;
                float db = 10.0f * log10f(lin);
                const unsigned long long XS = XS_OFF, PS = PS_SZ;
                if (osz >= XS + PS + 2ULL)      { out[XS+PS] = lin; out[XS+PS+1ULL] = db; }
                else if (osz == XS + 2ULL)      { out[XS] = lin; out[XS+1ULL] = db; }
                else if (osz == 2ULL)           { out[0] = lin; out[1] = db; }
                else if (osz == 1ULL)           { out[0] = db; }
                atomicExch(&g_ctr, 0u);
            }
        }
    }
}

extern "C" void kernel_launch(void* const* d_in, const int* in_sizes, int n_in,
                              void* d_out, int out_size)
{
    const float* X = (const float*)d_in[0];
    const float* Y = (const float*)d_in[1];
    const float* F = (const float*)d_in[2];
    const float* H = (const float*)d_in[3];
    const float* Q = (const float*)d_in[4];
    const float* R = (const float*)d_in[5];
    float* out = (float*)d_out;

    unsigned long long os = (unsigned long long)(long long)out_size;
    int wxs = (os >= XS_OFF) ? 1 : 0;
    int wps = (os >= XS_OFF + PS_SZ) ? 1 : 0;

    cudaFuncSetAttribute(ukf_kernel, cudaFuncAttributeMaxDynamicSharedMemorySize,
                         (int)sizeof(SM));
    ukf_kernel<<<NTRAJ, 256, sizeof(SM)>>>(X, Y, F, H, Q, R, out, wxs, wps, os);
}

// round 6
// speedup vs baseline: 1.5762x; 1.0523x over previous
#include <cuda_runtime.h>
#include <cstdint>
#include <cstddef>

#define NS 64
#define MO 32
#define NSIG 129
#define TSTEPS 250
#define NTRAJ 128
#define NT 512
#define DTC 0.02f
#define NLAM 63.0f
#define CW (0.5f/63.0f)
#define WM0 (-1.0f/63.0f)
#define WC0 (2.0f - 1.0f/63.0f)
#define WDIFF (WC0 - CW)
#define WMD (WM0 - CW)
#define XS_OFF 2048000ULL
#define PS_SZ  131072000ULL

typedef unsigned long long ull;

__device__ __forceinline__ void fma2(ull &d, ull a, ull b) {
    asm("fma.rn.f32x2 %0, %1, %2, %0;" : "+l"(d) : "l"(a), "l"(b));
}
__device__ __forceinline__ float hsum2(ull v) {
    return __uint_as_float((unsigned)v) + __uint_as_float((unsigned)(v >> 32));
}
__device__ __forceinline__ ull ld2s(const float* p) { return *reinterpret_cast<const ull*>(p); }
__device__ __forceinline__ void st2s(float* p, ull v) { *reinterpret_cast<ull*>(p) = v; }
__device__ __forceinline__ ull pk2(float x) {
    ull r; asm("mov.b64 %0, {%1, %1};" : "=l"(r) : "f"(x)); return r;
}
__device__ __forceinline__ float tanh_fast(float x) {
    float r; asm("tanh.approx.f32 %0, %1;" : "=f"(r) : "f"(x)); return r;
}

struct SM {
    float F[NS][66];
    float H[MO][66];
    float Qs[NS][66];
    float Rs[MO][33];
    float P[NS][66];
    float Achol[NS][66];   // column-major: Achol[j][i] = NLAM*(P+eps)
    float Lc[NS][66];      // Lc[k][d] = L[d][k]
    float Gk[NS][66];      // Gk[k][d] = sum_e Lc[k][e]*F[d][e]
    float dxT[NS][130];    // dxT[d][k]; col 129 = pad (0)
    float dzT[MO][130];
    float Pz[MO][33];
    float Pxz[NS][34];
    float Usm[NS][34];
    float pmean[8][66];
    float x[NS], xp[NS], innov[MO], zinv[MO], wsol[MO], row0[NS], yobs[MO];
    float red[16];
};

__device__ float g_mse[NTRAJ];
__device__ unsigned int g_ctr = 0;

__global__ __launch_bounds__(NT, 1)
void ukf_kernel(const float* __restrict__ gX, const float* __restrict__ gY,
                const float* __restrict__ gF, const float* __restrict__ gH,
                const float* __restrict__ gQ, const float* __restrict__ gR,
                float* __restrict__ out, int write_xs, int write_ps,
                unsigned long long osz)
{
    extern __shared__ unsigned char smem_raw[];
    SM& s = *reinterpret_cast<SM*>(smem_raw);
    const int tid = threadIdx.x;
    const int traj = blockIdx.x;

    // ---- init ----
    for (int idx = tid; idx < NS*NS; idx += NT) {
        int i = idx >> 6, j = idx & 63;
        s.F[i][j]  = gF[idx];
        s.Qs[i][j] = gQ[idx];
        s.Achol[j][i] = (i == j) ? NLAM * (1e-5f + 1e-8f) : 0.0f;
    }
    for (int idx = tid; idx < MO*NS; idx += NT) {
        int i = idx >> 6, j = idx & 63;
        s.H[i][j] = gH[idx];
    }
    for (int idx = tid; idx < MO*MO; idx += NT) {
        int i = idx >> 5, j = idx & 31;
        s.Rs[i][j] = gR[idx];
    }
    if (tid < NS) s.x[tid] = 0.0f;
    float mse_acc = 0.0f;

    for (int t = 0; t < TSTEPS; ++t) {
        // ======== phase 1: Cholesky-64, right-looking, 1 barrier/column ========
        {
            const int kk = tid & 63, pp = tid >> 6;   // pp 0..7
            for (int j = 0; j < NS; ++j) {
                __syncthreads();
                float ajj = s.Achol[j][j];
                float d = sqrtf(ajj);
                if (tid < NS)
                    s.Lc[j][tid] = (tid >= j) ? s.Achol[j][tid] / d : 0.0f;
                if (kk > j) {
                    ull cn = pk2(-(s.Achol[j][kk] / ajj));
                    #pragma unroll
                    for (int p = pp; p < 32; p += 8) {
                        ull av  = ld2s(&s.Achol[j][2*p]);
                        ull cur = ld2s(&s.Achol[kk][2*p]);
                        fma2(cur, av, cn);
                        st2s(&s.Achol[kk][2*p], cur);
                    }
                }
            }
        }
        __syncthreads();

        // ======== phase 2: Gk = Lc @ F^T; row0 = F@x; prefetch y ========
        {
            float yreg = 0.0f;
            if (tid < MO) yreg = gY[(size_t)traj * TSTEPS * MO + (size_t)t * MO + tid];
            int tk = tid & 15, td = tid >> 4;   // td 0..31
            ull acc[4][2];
            #pragma unroll
            for (int r = 0; r < 4; ++r) { acc[r][0] = 0ULL; acc[r][1] = 0ULL; }
            #pragma unroll 4
            for (int kp = 0; kp < 32; ++kp) {
                ull a0 = ld2s(&s.Lc[tk   ][2*kp]);
                ull a1 = ld2s(&s.Lc[tk+16][2*kp]);
                ull a2 = ld2s(&s.Lc[tk+32][2*kp]);
                ull a3 = ld2s(&s.Lc[tk+48][2*kp]);
                ull b0 = ld2s(&s.F[td   ][2*kp]);
                ull b1 = ld2s(&s.F[td+32][2*kp]);
                fma2(acc[0][0],a0,b0); fma2(acc[0][1],a0,b1);
                fma2(acc[1][0],a1,b0); fma2(acc[1][1],a1,b1);
                fma2(acc[2][0],a2,b0); fma2(acc[2][1],a2,b1);
                fma2(acc[3][0],a3,b0); fma2(acc[3][1],a3,b1);
            }
            #pragma unroll
            for (int r = 0; r < 4; ++r) {
                s.Gk[tk+16*r][td   ] = hsum2(acc[r][0]);
                s.Gk[tk+16*r][td+32] = hsum2(acc[r][1]);
            }
            if (tid < NS) {
                ull rc = 0ULL;
                #pragma unroll 4
                for (int kp = 0; kp < 32; ++kp)
                    fma2(rc, ld2s(&s.x[2*kp]), ld2s(&s.F[tid][2*kp]));
                s.row0[tid] = hsum2(rc);
            }
            if (tid < MO) s.yobs[tid] = yreg;
        }
        __syncthreads();

        // ======== phase 3: sf element-wise, stored transposed into dxT ========
        for (int idx = tid; idx < 130*NS; idx += NT) {
            int r = idx >> 6, d = idx & 63;
            float v;
            if (r == 129) v = 0.0f;
            else {
                float base = s.x[d], arg = s.row0[d];
                if (r >= 1) {
                    int k = (r <= NS) ? r - 1 : r - 1 - NS;
                    float lv = s.Lc[k][d], gv = s.Gk[k][d];
                    if (r <= NS) { base += lv; arg += gv; }
                    else         { base -= lv; arg -= gv; }
                }
                v = base + DTC * tanh_fast(arg);
            }
            s.dxT[d][r] = v;
        }
        __syncthreads();

        // ======== phase 4a: xp partial sums (8 per row) ========
        {
            int d = tid >> 3, g = tid & 7;
            ull acc = 0ULL;
            const ull one2 = pk2(1.0f);
            for (int kp = g; kp < 65; kp += 8)
                fma2(acc, ld2s(&s.dxT[d][2*kp]), one2);
            s.pmean[g][d] = hsum2(acc);
        }
        __syncthreads();
        // ======== phase 4b: combine xp ========
        if (tid < NS) {
            float S = ((s.pmean[0][tid] + s.pmean[1][tid]) + (s.pmean[2][tid] + s.pmean[3][tid]))
                    + ((s.pmean[4][tid] + s.pmean[5][tid]) + (s.pmean[6][tid] + s.pmean[7][tid]));
            s.xp[tid] = CW * S + WMD * s.dxT[tid][0];
        }
        __syncthreads();

        // ======== phase 5: center dxT in place | warp0: innov = y - H@xp ========
        if (tid < 32) {
            ull acc = 0ULL;
            #pragma unroll 4
            for (int kp = 0; kp < 32; ++kp)
                fma2(acc, ld2s(&s.H[tid][2*kp]), ld2s(&s.xp[2*kp]));
            s.innov[tid] = s.yobs[tid] - hsum2(acc);
        } else {
            for (int idx = tid - 32; idx < 130*NS; idx += NT - 32) {
                int d = idx / 130, k = idx - d * 130;
                float v = (k < 129) ? s.dxT[d][k] - s.xp[d] : 0.0f;
                s.dxT[d][k] = v;
            }
        }
        __syncthreads();

        // ======== phase 6: dzT = H @ dx ========
        {
            int ti = tid & 15, g = tid >> 4;   // g 0..31
            ull a00=0ULL,a01=0ULL,a10=0ULL,a11=0ULL, e0=0ULL, e1=0ULL;
            bool extra = (g == 31);
            for (int d = 0; d < NS; ++d) {
                ull h0 = pk2(s.H[ti   ][d]);
                ull h1 = pk2(s.H[ti+16][d]);
                ull b0 = ld2s(&s.dxT[d][2*g]);
                ull b1 = ld2s(&s.dxT[d][2*(g+32)]);
                fma2(a00,h0,b0); fma2(a01,h0,b1);
                fma2(a10,h1,b0); fma2(a11,h1,b1);
                if (extra) {
                    ull b2 = ld2s(&s.dxT[d][128]);
                    fma2(e0,h0,b2); fma2(e1,h1,b2);
                }
            }
            st2s(&s.dzT[ti   ][2*g],      a00);
            st2s(&s.dzT[ti   ][2*(g+32)], a01);
            st2s(&s.dzT[ti+16][2*g],      a10);
            st2s(&s.dzT[ti+16][2*(g+32)], a11);
            if (extra) {
                st2s(&s.dzT[ti   ][128], e0);
                st2s(&s.dzT[ti+16][128], e1);
            }
        }
        __syncthreads();

        // ======== phase 7: Pz gram (2 outputs/thread) ========
        {
            int ti = tid & 15, tj = tid >> 4;   // tj 0..31
            ull a0 = 0ULL, a1 = 0ULL;
            #pragma unroll 2
            for (int kp = 0; kp < 65; ++kp) {
                ull b  = ld2s(&s.dzT[tj][2*kp]);
                fma2(a0, ld2s(&s.dzT[ti   ][2*kp]), b);
                fma2(a1, ld2s(&s.dzT[ti+16][2*kp]), b);
            }
            float bz = s.dzT[tj][0];
            s.Pz[ti   ][tj] = CW*hsum2(a0) + WDIFF * s.dzT[ti   ][0]*bz + s.Rs[ti   ][tj];
            s.Pz[ti+16][tj] = CW*hsum2(a1) + WDIFF * s.dzT[ti+16][0]*bz + s.Rs[ti+16][tj];
        }
        __syncthreads();

        // ======== phase 8: warp0 chol32(Pz) | others P_pred + Pxz grams ========
        if (tid < 32) {
            int lane = tid;
            for (int j = 0; j < MO; ++j) {
                float c = 0.0f;
                if (lane >= j) {
                    c = s.Pz[lane][j];
                    float c0=0.f, c1=0.f; int k = 0;
                    for (; k + 1 < j; k += 2) {
                        c0 += s.Pz[lane][k]   * s.Pz[j][k];
                        c1 += s.Pz[lane][k+1] * s.Pz[j][k+1];
                    }
                    if (k < j) c0 += s.Pz[lane][k] * s.Pz[j][k];
                    c -= c0 + c1;
                }
                float cj = __shfl_sync(0xffffffffu, c, j);
                float d = sqrtf(cj);
                if (lane == j)      { s.Pz[j][j] = d; s.zinv[j] = 1.0f / d; }
                else if (lane > j)  { s.Pz[lane][j] = c / d; }
                __syncwarp();
            }
        } else {
            for (int idx = tid - 32; idx < 1536; idx += NT - 32) {
                if (idx < 1024) {
                    // P_pred 2x2: rows {ti, ti+32}, cols {tj, tj+32}
                    int ti = idx & 31, tj = idx >> 5;
                    ull a00=0ULL,a01=0ULL,a10=0ULL,a11=0ULL;
                    #pragma unroll 2
                    for (int kp = 0; kp < 65; ++kp) {
                        ull r0 = ld2s(&s.dxT[ti   ][2*kp]);
                        ull r1 = ld2s(&s.dxT[ti+32][2*kp]);
                        ull c0 = ld2s(&s.dxT[tj   ][2*kp]);
                        ull c1 = ld2s(&s.dxT[tj+32][2*kp]);
                        fma2(a00,r0,c0); fma2(a01,r0,c1);
                        fma2(a10,r1,c0); fma2(a11,r1,c1);
                    }
                    float x0 = s.dxT[ti][0], x1 = s.dxT[ti+32][0];
                    float y0 = s.dxT[tj][0], y1 = s.dxT[tj+32][0];
                    s.P[ti   ][tj   ] = CW*hsum2(a00) + WDIFF*x0*y0 + s.Qs[ti   ][tj   ];
                    s.P[ti   ][tj+32] = CW*hsum2(a01) + WDIFF*x0*y1 + s.Qs[ti   ][tj+32];
                    s.P[ti+32][tj   ] = CW*hsum2(a10) + WDIFF*x1*y0 + s.Qs[ti+32][tj   ];
                    s.P[ti+32][tj+32] = CW*hsum2(a11) + WDIFF*x1*y1 + s.Qs[ti+32][tj+32];
                } else {
                    // Pxz 2x2: rows {ti, ti+32}, cols {tj, tj+16}
                    int q = idx - 1024;
                    int ti = q & 31, tj = q >> 5;   // tj 0..15
                    ull a00=0ULL,a01=0ULL,a10=0ULL,a11=0ULL;
                    #pragma unroll 2
                    for (int kp = 0; kp < 65; ++kp) {
                        ull r0 = ld2s(&s.dxT[ti   ][2*kp]);
                        ull r1 = ld2s(&s.dxT[ti+32][2*kp]);
                        ull c0 = ld2s(&s.dzT[tj   ][2*kp]);
                        ull c1 = ld2s(&s.dzT[tj+16][2*kp]);
                        fma2(a00,r0,c0); fma2(a01,r0,c1);
                        fma2(a10,r1,c0); fma2(a11,r1,c1);
                    }
                    float x0 = s.dxT[ti][0], x1 = s.dxT[ti+32][0];
                    float z0 = s.dzT[tj][0], z1 = s.dzT[tj+16][0];
                    s.Pxz[ti   ][tj   ] = CW*hsum2(a00) + WDIFF*x0*z0;
                    s.Pxz[ti   ][tj+16] = CW*hsum2(a01) + WDIFF*x0*z1;
                    s.Pxz[ti+32][tj   ] = CW*hsum2(a10) + WDIFF*x1*z0;
                    s.Pxz[ti+32][tj+16] = CW*hsum2(a11) + WDIFF*x1*z1;
                }
            }
        }
        __syncthreads();

        // ======== phase 9: forward solves L*[U|w] = [Pxz^T|innov] ========
        if (tid < NS + 1) {
            float v[MO];
            if (tid < NS) {
                #pragma unroll
                for (int m = 0; m < MO; ++m) v[m] = s.Pxz[tid][m];
            } else {
                #pragma unroll
                for (int m = 0; m < MO; ++m) v[m] = s.innov[m];
            }
            #pragma unroll
            for (int i = 0; i < MO; ++i) {
                float acc = v[i];
                #pragma unroll
                for (int j = 0; j < i; ++j) acc -= s.Pz[i][j] * v[j];
                v[i] = acc * s.zinv[i];
            }
            if (tid < NS) {
                #pragma unroll
                for (int m = 0; m < MO; ++m) s.Usm[tid][m] = v[m];
            } else {
                #pragma unroll
                for (int m = 0; m < MO; ++m) s.wsol[m] = v[m];
            }
        }
        __syncthreads();

        // ======== phase 10: x_new + (P_new = P - U^T U) -> next Achol ========
        if (tid < NS) {
            float xn = s.xp[tid];
            #pragma unroll
            for (int m = 0; m < MO; ++m) xn += s.Usm[tid][m] * s.wsol[m];
            s.x[tid] = xn;
            size_t oidx = ((size_t)traj * TSTEPS + t) * NS + tid;
            if (write_xs) out[oidx] = xn;
            float de = xn - gX[oidx];
            mse_acc += de * de;
        }
        {
            int ti = tid & 31, tj = tid >> 5;   // tj 0..15
            ull acc[2][4];
            #pragma unroll
            for (int r = 0; r < 2; ++r)
                #pragma unroll
                for (int c = 0; c < 4; ++c) acc[r][c] = 0ULL;
            #pragma unroll 4
            for (int mp = 0; mp < 16; ++mp) {
                ull r0 = ld2s(&s.Usm[ti   ][2*mp]);
                ull r1 = ld2s(&s.Usm[ti+32][2*mp]);
                ull c0 = ld2s(&s.Usm[tj   ][2*mp]);
                ull c1 = ld2s(&s.Usm[tj+16][2*mp]);
                ull c2 = ld2s(&s.Usm[tj+32][2*mp]);
                ull c3 = ld2s(&s.Usm[tj+48][2*mp]);
                fma2(acc[0][0],r0,c0); fma2(acc[0][1],r0,c1); fma2(acc[0][2],r0,c2); fma2(acc[0][3],r0,c3);
                fma2(acc[1][0],r1,c0); fma2(acc[1][1],r1,c1); fma2(acc[1][2],r1,c2); fma2(acc[1][3],r1,c3);
            }
            #pragma unroll
            for (int r = 0; r < 2; ++r)
                #pragma unroll
                for (int c = 0; c < 4; ++c) {
                    int i = ti + 32*r, j = tj + 16*c;
                    float pv = s.P[i][j] - hsum2(acc[r][c]);
                    s.Achol[j][i] = NLAM * (pv + ((i == j) ? 1e-8f : 0.0f));
                    if (write_ps)
                        out[XS_OFF + (((size_t)traj * TSTEPS + t) << 12) + (size_t)i*NS + j] = pv;
                }
        }
        __syncthreads();
    }

    // ---- per-trajectory MSE + merged finalize ----
    {
        float v = (tid < NS) ? mse_acc : 0.0f;
        for (int o = 16; o > 0; o >>= 1) v += __shfl_down_sync(0xffffffffu, v, o);
        if ((tid & 31) == 0) s.red[tid >> 5] = v;
        __syncthreads();
        if (tid == 0) {
            g_mse[traj] = (s.red[0] + s.red[1]) * (1.0f / (float)(TSTEPS * NS));
            __threadfence();
            unsigned int prev = atomicAdd(&g_ctr, 1u);
            if (prev == NTRAJ - 1) {
                __threadfence();
                float tot = 0.0f;
                for (int i = 0; i < NTRAJ; ++i) tot += g_mse[i];
                float lin = tot / (float)NTRAJ;
                float db = 10.0f * log10f(lin);
                const unsigned long long XS = XS_OFF, PS = PS_SZ;
                if (osz >= XS + PS + 2ULL)      { out[XS+PS] = lin; out[XS+PS+1ULL] = db; }
                else if (osz == XS + 2ULL)      { out[XS] = lin; out[XS+1ULL] = db; }
                else if (osz == 2ULL)           { out[0] = lin; out[1] = db; }
                else if (osz == 1ULL)           { out[0] = db; }
                atomicExch(&g_ctr, 0u);
            }
        }
    }
}

extern "C" void kernel_launch(void* const* d_in, const int* in_sizes, int n_in,
                              void* d_out, int out_size)
{
    const float* X = (const float*)d_in[0];
    const float* Y = (const float*)d_in[1];
    const float* F = (const float*)d_in[2];
    const float* H = (const float*)d_in[3];
    const float* Q = (const float*)d_in[4];
    const float* R = (const float*)d_in[5];
    float* out = (float*)d_out;

    unsigned long long os = (unsigned long long)(long long)out_size;
    int wxs = (os >= XS_OFF) ? 1 : 0;
    int wps = (os >= XS_OFF + PS_SZ) ? 1 : 0;

    cudaFuncSetAttribute(ukf_kernel, cudaFuncAttributeMaxDynamicSharedMemorySize,
                         (int)sizeof(SM));
    ukf_kernel<<<NTRAJ, NT, sizeof(SM)>>>(X, Y, F, H, Q, R, out, wxs, wps, os);
}